// round 13
// baseline (speedup 1.0000x reference)
#include <cuda_runtime.h>
#include <cuda_fp16.h>
#include <cstdint>

// Problem constants
#define B_  4
#define T_  2048
#define C_  1024
#define H_  16
#define D_  64
#define M_  (B_ * T_)      // 8192 rows
#define W3_ (3 * C_)       // 3072

// Scratch (allocation-free rule: __device__ globals), all pre-split half data
__device__ __half g_xhi[(size_t)M_ * C_];
__device__ __half g_xlo[(size_t)M_ * C_];
__device__ __half g_wahi[(size_t)W3_ * C_];   // w_attn transposed [N][K]
__device__ __half g_walo[(size_t)W3_ * C_];
__device__ __half g_wphi[(size_t)C_ * C_];    // w_proj transposed [N][K]
__device__ __half g_wplo[(size_t)C_ * C_];
__device__ __half g_qkvhi[(size_t)M_ * W3_];
__device__ __half g_qkvlo[(size_t)M_ * W3_];
__device__ __half g_yhi[(size_t)M_ * C_];
__device__ __half g_ylo[(size_t)M_ * C_];

// ---------------------------------------------------------------------------
// helpers
// ---------------------------------------------------------------------------
__device__ __forceinline__ void mma_f16(float* acc, const uint32_t* a,
                                        const uint32_t* b) {
    asm volatile(
        "mma.sync.aligned.m16n8k16.row.col.f32.f16.f16.f32 "
        "{%0,%1,%2,%3}, {%4,%5,%6,%7}, {%8,%9}, {%0,%1,%2,%3};"
        : "+f"(acc[0]), "+f"(acc[1]), "+f"(acc[2]), "+f"(acc[3])
        : "r"(a[0]), "r"(a[1]), "r"(a[2]), "r"(a[3]),
          "r"(b[0]), "r"(b[1]));
}

__device__ __forceinline__ void split2(float x, float y, __half2& hi, __half2& lo) {
    hi = __float22half2_rn(make_float2(x, y));
    float2 h = __half22float2(hi);
    lo = __float22half2_rn(make_float2(x - h.x, y - h.y));
}

__device__ __forceinline__ uint32_t h2u(__half2 v) { return *(uint32_t*)&v; }

__device__ __forceinline__ float ex2f(float x) {
    float y;
    asm("ex2.approx.f32 %0, %1;" : "=f"(y) : "f"(x));
    return y;
}

__device__ __forceinline__ uint32_t smem_u32(const void* p) {
    uint32_t a;
    asm("{ .reg .u64 t; cvta.to.shared.u64 t, %1; cvt.u32.u64 %0, t; }"
        : "=r"(a) : "l"(p));
    return a;
}

__device__ __forceinline__ void ldsm_x4(uint32_t* r, uint32_t addr) {
    asm volatile("ldmatrix.sync.aligned.m8n8.x4.shared.b16 {%0,%1,%2,%3}, [%4];"
                 : "=r"(r[0]), "=r"(r[1]), "=r"(r[2]), "=r"(r[3]) : "r"(addr));
}
__device__ __forceinline__ void ldsm_x4_t(uint32_t* r, uint32_t addr) {
    asm volatile("ldmatrix.sync.aligned.m8n8.x4.trans.shared.b16 {%0,%1,%2,%3}, [%4];"
                 : "=r"(r[0]), "=r"(r[1]), "=r"(r[2]), "=r"(r[3]) : "r"(addr));
}

__device__ __forceinline__ void cp16(uint32_t saddr, const void* gptr) {
    asm volatile("cp.async.cg.shared.global [%0], [%1], 16;"
                 :: "r"(saddr), "l"(gptr) : "memory");
}
#define CP_COMMIT() asm volatile("cp.async.commit_group;" ::: "memory")
#define CP_WAIT(n)  asm volatile("cp.async.wait_group %0;" :: "n"(n) : "memory")

// ---------------------------------------------------------------------------
// Converter kernels
// ---------------------------------------------------------------------------
__global__ void __launch_bounds__(256) convert_x_kernel(
    const float* __restrict__ x, __half* __restrict__ xhi,
    __half* __restrict__ xlo, int n4)
{
    int i = blockIdx.x * 256 + threadIdx.x;
    if (i >= n4) return;
    float4 v = *(const float4*)(x + 4 * (size_t)i);
    __half2 h01, l01, h23, l23;
    split2(v.x, v.y, h01, l01);
    split2(v.z, v.w, h23, l23);
    *(__half2*)&xhi[4 * (size_t)i]     = h01;
    *(__half2*)&xhi[4 * (size_t)i + 2] = h23;
    *(__half2*)&xlo[4 * (size_t)i]     = l01;
    *(__half2*)&xlo[4 * (size_t)i + 2] = l23;
}

// W [K][N] fp32 -> Whi/Wlo [N][K] halves (transpose + split)
__global__ void __launch_bounds__(256) convert_wT_kernel(
    const float* __restrict__ W, __half* __restrict__ whi,
    __half* __restrict__ wlo, int K, int N)
{
    __shared__ float tile[32][33];
    const int tx = threadIdx.x & 31;
    const int ty = threadIdx.x >> 5;
    const int n0 = blockIdx.x * 32;
    const int k0 = blockIdx.y * 32;
    #pragma unroll
    for (int i = ty; i < 32; i += 8)
        tile[i][tx] = W[(size_t)(k0 + i) * N + n0 + tx];
    __syncthreads();
    #pragma unroll
    for (int i = ty; i < 32; i += 8) {
        float v = tile[tx][i];
        __half h = __float2half_rn(v);
        __half l = __float2half_rn(v - __half2float(h));
        whi[(size_t)(n0 + i) * K + k0 + tx] = h;
        wlo[(size_t)(n0 + i) * K + k0 + tx] = l;
    }
}

// ---------------------------------------------------------------------------
// Split-fp16 tensor GEMM. three_term=1: hh+hl+lh; three_term=0: hh+lh only
// (B-lo never loaded/copied — used for proj where error budget allows).
// 128x128 CTA tile, BK=32, 256 threads (8 warps 4Mx2N), cp.async pipeline.
// ---------------------------------------------------------------------------
#define APITCH 40
#define ST_ALO 10240
#define ST_BHI 20480
#define ST_BLO 30720
#define STAGE_B 40960
#define GEMM_SMEM_BYTES (2 * STAGE_B)     // 81920

__global__ void __launch_bounds__(256, 2) gemm_h_kernel(
    const __half* __restrict__ Ahi_g, const __half* __restrict__ Alo_g,
    const __half* __restrict__ Bhi_g, const __half* __restrict__ Blo_g,
    const float* __restrict__ bias,
    float* __restrict__ Out, __half* __restrict__ Ohi, __half* __restrict__ Olo,
    int write_split, int three_term, int M, int K, int N)
{
    extern __shared__ __half smh[];

    const int tid  = threadIdx.x;
    const int w    = tid >> 5;
    const int lane = tid & 31;
    const int g    = lane >> 2;
    const int tig  = lane & 3;
    const int wm   = (w & 3) * 32;
    const int wn   = (w >> 2) * 64;

    const int lrow16 = lane & 15;
    const int lhi8   = (lane & 16) >> 1;
    const int l8     = lane & 8;

    const int bm = blockIdx.y * 128;
    const int bn = blockIdx.x * 128;

    const int sr = tid >> 2;          // 0..63 (+64)
    const int sc = tid & 3;           // 16B chunk within row

    const uint32_t sbase = smem_u32(smh);

    float acc[2][8][4] = {};

    const int nchunk = K >> 5;

    const __half* gA  = Ahi_g + (size_t)(bm + sr) * K + 8 * sc;
    const __half* gAl = Alo_g + (size_t)(bm + sr) * K + 8 * sc;
    const __half* gB  = Bhi_g + (size_t)(bn + sr) * K + 8 * sc;
    const __half* gBl = Blo_g + (size_t)(bn + sr) * K + 8 * sc;
    const size_t rstep = 64 * (size_t)K;

    auto issue = [&](int c, int buf) {
        const int k0 = c << 5;
        const uint32_t S = sbase + (buf ? STAGE_B : 0);
        #pragma unroll
        for (int l = 0; l < 2; l++) {
            const uint32_t off = (uint32_t)(sr + 64 * l) * 80 + 16 * sc;
            cp16(S + off,          gA  + l * rstep + k0);
            cp16(S + ST_ALO + off, gAl + l * rstep + k0);
            cp16(S + ST_BHI + off, gB  + l * rstep + k0);
            if (three_term)
                cp16(S + ST_BLO + off, gBl + l * rstep + k0);
        }
        CP_COMMIT();
    };

    issue(0, 0);

    for (int c = 0; c < nchunk; c++) {
        CP_WAIT(0);
        __syncthreads();
        if (c + 1 < nchunk) issue(c + 1, (c + 1) & 1);

        const uint32_t sA = sbase + ((c & 1) ? STAGE_B : 0);

        #pragma unroll
        for (int ks = 0; ks < 2; ks++) {
            uint32_t ah[2][4], al[2][4];
            #pragma unroll
            for (int ti = 0; ti < 2; ti++) {
                const uint32_t aoff =
                    2 * ((wm + (ti << 4) + lrow16) * APITCH + (ks << 4) + lhi8);
                ldsm_x4(ah[ti], sA + aoff);
                ldsm_x4(al[ti], sA + ST_ALO + aoff);
            }
            #pragma unroll
            for (int jp = 0; jp < 4; jp++) {
                const uint32_t boff =
                    2 * ((wn + (jp << 4) + (lane & 7) + lhi8) * APITCH + (ks << 4) + l8);
                uint32_t bh[4], bl[4];
                ldsm_x4(bh, sA + ST_BHI + boff);
                if (three_term) ldsm_x4(bl, sA + ST_BLO + boff);
                // term-major ordering: same-acc distance = 4
                mma_f16(acc[0][2 * jp],     ah[0], bh);
                mma_f16(acc[0][2 * jp + 1], ah[0], bh + 2);
                mma_f16(acc[1][2 * jp],     ah[1], bh);
                mma_f16(acc[1][2 * jp + 1], ah[1], bh + 2);
                if (three_term) {
                    mma_f16(acc[0][2 * jp],     ah[0], bl);
                    mma_f16(acc[0][2 * jp + 1], ah[0], bl + 2);
                    mma_f16(acc[1][2 * jp],     ah[1], bl);
                    mma_f16(acc[1][2 * jp + 1], ah[1], bl + 2);
                }
                mma_f16(acc[0][2 * jp],     al[0], bh);
                mma_f16(acc[0][2 * jp + 1], al[0], bh + 2);
                mma_f16(acc[1][2 * jp],     al[1], bh);
                mma_f16(acc[1][2 * jp + 1], al[1], bh + 2);
            }
        }
    }

    // ---- epilogue ----
    if (write_split) {
        #pragma unroll
        for (int j = 0; j < 8; j++) {
            const int col = bn + wn + (j << 3) + (tig << 1);
            const float2 bb = *(const float2*)(bias + col);
            #pragma unroll
            for (int ti = 0; ti < 2; ti++) {
                const int row = bm + wm + (ti << 4) + g;
                __half2 hh, ll;
                split2(acc[ti][j][0] + bb.x, acc[ti][j][1] + bb.y, hh, ll);
                *(__half2*)&Ohi[(size_t)row * N + col] = hh;
                *(__half2*)&Olo[(size_t)row * N + col] = ll;
                split2(acc[ti][j][2] + bb.x, acc[ti][j][3] + bb.y, hh, ll);
                *(__half2*)&Ohi[(size_t)(row + 8) * N + col] = hh;
                *(__half2*)&Olo[(size_t)(row + 8) * N + col] = ll;
            }
        }
    } else {
        #pragma unroll
        for (int j = 0; j < 8; j++) {
            const int col = bn + wn + (j << 3) + (tig << 1);
            const float2 bb = *(const float2*)(bias + col);
            #pragma unroll
            for (int ti = 0; ti < 2; ti++) {
                const int row = bm + wm + (ti << 4) + g;
                float2 o0, o1;
                o0.x = acc[ti][j][0] + bb.x;
                o0.y = acc[ti][j][1] + bb.y;
                o1.x = acc[ti][j][2] + bb.x;
                o1.y = acc[ti][j][3] + bb.y;
                *(float2*)(Out + (size_t)row * N + col)       = o0;
                *(float2*)(Out + (size_t)(row + 8) * N + col) = o1;
            }
        }
    }
}

// ---------------------------------------------------------------------------
// Split-fp16 TC causal flash attention.
// exp2-domain softmax (scale = 8*log2e, raw EX2), warp-uniform mask skip
// for fully-valid tiles, qi reversal for causal load balance.
// ---------------------------------------------------------------------------
#define KPITCH 72
#define KV_STAGE 36864
#define AK_LO_B (64 * KPITCH * 2)
#define AV_HI_B (2 * 64 * KPITCH * 2)
#define AV_LO_B (3 * 64 * KPITCH * 2)
#define AQ_LO_B (128 * KPITCH * 2)
#define KV_BASE 36864
#define ATTN_TC_SMEM (KV_BASE + 2 * KV_STAGE)   // 110592
#define SM_SCALE 11.5415603f                     // 8 * log2(e)

__global__ void __launch_bounds__(256, 2) attn_tc_kernel(
    const __half* __restrict__ qkvhi, const __half* __restrict__ qkvlo,
    __half* __restrict__ yhi, __half* __restrict__ ylo)
{
    extern __shared__ __half sha[];

    const int tid  = threadIdx.x;
    const int w    = tid >> 5;
    const int lane = tid & 31;
    const int g    = lane >> 2;
    const int tig  = lane & 3;
    const int lrow16 = lane & 15;
    const int lhi8   = (lane & 16) >> 1;
    const int l8     = lane & 8;
    const int qi   = gridDim.x - 1 - blockIdx.x;   // heaviest CTAs first
    const int h    = blockIdx.y;
    const int b    = blockIdx.z;
    const int qblock = qi * 128;

    const uint32_t sbase = smem_u32(sha);
    const size_t rowbase = (size_t)b * T_ * W3_ + h * D_;

    const int sr = tid >> 3;
    const int sc = tid & 7;

    auto issue_kv = [&](int kj, int buf) {
        const uint32_t S = sbase + KV_BASE + (buf ? KV_STAGE : 0);
        #pragma unroll
        for (int l = 0; l < 2; l++) {
            const int r = sr + 32 * l;
            const size_t src = rowbase + (size_t)(kj * 64 + r) * W3_ + 8 * sc;
            const uint32_t off = (uint32_t)r * 144 + 16 * sc;
            cp16(S + off,           qkvhi + src + C_);
            cp16(S + AK_LO_B + off, qkvlo + src + C_);
            cp16(S + AV_HI_B + off, qkvhi + src + 2 * C_);
            cp16(S + AV_LO_B + off, qkvlo + src + 2 * C_);
        }
        CP_COMMIT();
    };

    issue_kv(0, 0);

    {
        char* S = (char*)sha;
        #pragma unroll
        for (int l = 0; l < 4; l++) {
            const int r = sr + 32 * l;
            const size_t src = rowbase + (size_t)(qblock + r) * W3_ + 8 * sc;
            const int off = r * 144 + 16 * sc;
            *(uint4*)(S + off)           = *(const uint4*)(qkvhi + src);
            *(uint4*)(S + AQ_LO_B + off) = *(const uint4*)(qkvlo + src);
        }
    }
    __syncthreads();

    uint32_t qh[4][4], ql[4][4];
    #pragma unroll
    for (int kc = 0; kc < 4; kc++) {
        const uint32_t qoff = 2 * (((w << 4) + lrow16) * KPITCH + (kc << 4) + lhi8);
        ldsm_x4(qh[kc], sbase + qoff);
        ldsm_x4(ql[kc], sbase + AQ_LO_B + qoff);
    }

    const int row0 = qblock + (w << 4) + g;
    const int row1 = row0 + 8;
    const int rowmin = qblock + (w << 4);

    float m0 = -1e30f, m1 = -1e30f, l0 = 0.0f, l1 = 0.0f;
    float o[8][4] = {};

    const int nkj = 2 * qi + 2;

    for (int kj = 0; kj < nkj; kj++) {
        CP_WAIT(0);
        __syncthreads();
        if (kj + 1 < nkj) issue_kv(kj + 1, (kj + 1) & 1);

        const uint32_t sKV = sbase + KV_BASE + ((kj & 1) ? KV_STAGE : 0);

        // ---- S = Q @ K^T ----
        float sacc[8][4] = {};
        #pragma unroll
        for (int kc = 0; kc < 4; kc++) {
            #pragma unroll
            for (int jnp = 0; jnp < 4; jnp++) {
                const uint32_t koff =
                    2 * (((jnp << 4) + (lane & 7) + lhi8) * KPITCH + (kc << 4) + l8);
                uint32_t kh[4], kl[4];
                ldsm_x4(kh, sKV + koff);
                ldsm_x4(kl, sKV + AK_LO_B + koff);
                mma_f16(sacc[2 * jnp],     qh[kc], kh);
                mma_f16(sacc[2 * jnp + 1], qh[kc], kh + 2);
                mma_f16(sacc[2 * jnp],     qh[kc], kl);
                mma_f16(sacc[2 * jnp + 1], qh[kc], kl + 2);
                mma_f16(sacc[2 * jnp],     ql[kc], kh);
                mma_f16(sacc[2 * jnp + 1], ql[kc], kh + 2);
            }
        }

        // ---- scale (exp2 domain), mask only on diagonal tiles ----
        float tm0 = -1e30f, tm1 = -1e30f;
        if (kj * 64 + 63 <= rowmin) {
            // fully valid tile for this warp: no masking needed
            #pragma unroll
            for (int jn = 0; jn < 8; jn++) {
                float v0 = sacc[jn][0] * SM_SCALE;
                float v1 = sacc[jn][1] * SM_SCALE;
                float v2 = sacc[jn][2] * SM_SCALE;
                float v3 = sacc[jn][3] * SM_SCALE;
                sacc[jn][0] = v0; sacc[jn][1] = v1;
                sacc[jn][2] = v2; sacc[jn][3] = v3;
                tm0 = fmaxf(tm0, fmaxf(v0, v1));
                tm1 = fmaxf(tm1, fmaxf(v2, v3));
            }
        } else {
            #pragma unroll
            for (int jn = 0; jn < 8; jn++) {
                const int c0 = kj * 64 + (jn << 3) + (tig << 1);
                float v0 = (c0     <= row0) ? sacc[jn][0] * SM_SCALE : -1e30f;
                float v1 = (c0 + 1 <= row0) ? sacc[jn][1] * SM_SCALE : -1e30f;
                float v2 = (c0     <= row1) ? sacc[jn][2] * SM_SCALE : -1e30f;
                float v3 = (c0 + 1 <= row1) ? sacc[jn][3] * SM_SCALE : -1e30f;
                sacc[jn][0] = v0; sacc[jn][1] = v1;
                sacc[jn][2] = v2; sacc[jn][3] = v3;
                tm0 = fmaxf(tm0, fmaxf(v0, v1));
                tm1 = fmaxf(tm1, fmaxf(v2, v3));
            }
        }
        tm0 = fmaxf(tm0, __shfl_xor_sync(0xffffffffu, tm0, 1));
        tm0 = fmaxf(tm0, __shfl_xor_sync(0xffffffffu, tm0, 2));
        tm1 = fmaxf(tm1, __shfl_xor_sync(0xffffffffu, tm1, 1));
        tm1 = fmaxf(tm1, __shfl_xor_sync(0xffffffffu, tm1, 2));

        const float mn0 = fmaxf(m0, tm0);
        const float mn1 = fmaxf(m1, tm1);
        const float al0 = ex2f(m0 - mn0);
        const float al1 = ex2f(m1 - mn1);
        m0 = mn0; m1 = mn1;

        float s0 = 0.0f, s1 = 0.0f;
        #pragma unroll
        for (int jn = 0; jn < 8; jn++) {
            float p0 = ex2f(sacc[jn][0] - mn0);
            float p1 = ex2f(sacc[jn][1] - mn0);
            float p2 = ex2f(sacc[jn][2] - mn1);
            float p3 = ex2f(sacc[jn][3] - mn1);
            sacc[jn][0] = p0; sacc[jn][1] = p1;
            sacc[jn][2] = p2; sacc[jn][3] = p3;
            s0 += p0 + p1;
            s1 += p2 + p3;
        }
        s0 += __shfl_xor_sync(0xffffffffu, s0, 1);
        s0 += __shfl_xor_sync(0xffffffffu, s0, 2);
        s1 += __shfl_xor_sync(0xffffffffu, s1, 1);
        s1 += __shfl_xor_sync(0xffffffffu, s1, 2);
        l0 = l0 * al0 + s0;
        l1 = l1 * al1 + s1;

        // ---- rescale O, then O += P @ V ----
        #pragma unroll
        for (int jd = 0; jd < 8; jd++) {
            o[jd][0] *= al0; o[jd][1] *= al0;
            o[jd][2] *= al1; o[jd][3] *= al1;
        }

        #pragma unroll
        for (int kc = 0; kc < 4; kc++) {
            uint32_t ph[4], pl[4];
            {
                __half2 hh, ll;
                split2(sacc[2 * kc][0], sacc[2 * kc][1], hh, ll);
                ph[0] = h2u(hh); pl[0] = h2u(ll);
                split2(sacc[2 * kc][2], sacc[2 * kc][3], hh, ll);
                ph[1] = h2u(hh); pl[1] = h2u(ll);
                split2(sacc[2 * kc + 1][0], sacc[2 * kc + 1][1], hh, ll);
                ph[2] = h2u(hh); pl[2] = h2u(ll);
                split2(sacc[2 * kc + 1][2], sacc[2 * kc + 1][3], hh, ll);
                ph[3] = h2u(hh); pl[3] = h2u(ll);
            }
            #pragma unroll
            for (int jdp = 0; jdp < 4; jdp++) {
                const uint32_t voff =
                    2 * (((kc << 4) + lrow16) * KPITCH + (jdp << 4) + lhi8);
                uint32_t vh[4], vl[4];
                ldsm_x4_t(vh, sKV + AV_HI_B + voff);
                ldsm_x4_t(vl, sKV + AV_LO_B + voff);
                mma_f16(o[2 * jdp],     ph, vh);
                mma_f16(o[2 * jdp + 1], ph, vh + 2);
                mma_f16(o[2 * jdp],     ph, vl);
                mma_f16(o[2 * jdp + 1], ph, vl + 2);
                mma_f16(o[2 * jdp],     pl, vh);
                mma_f16(o[2 * jdp + 1], pl, vh + 2);
            }
        }
    }

    const float inv0 = 1.0f / l0;
    const float inv1 = 1.0f / l1;
    const size_t y0 = (size_t)(b * T_ + row0) * C_ + h * D_ + (tig << 1);
    const size_t y1 = y0 + 8 * (size_t)C_;
    #pragma unroll
    for (int jd = 0; jd < 8; jd++) {
        __half2 hh, ll;
        split2(o[jd][0] * inv0, o[jd][1] * inv0, hh, ll);
        *(__half2*)&yhi[y0 + (jd << 3)] = hh;
        *(__half2*)&ylo[y0 + (jd << 3)] = ll;
        split2(o[jd][2] * inv1, o[jd][3] * inv1, hh, ll);
        *(__half2*)&yhi[y1 + (jd << 3)] = hh;
        *(__half2*)&ylo[y1 + (jd << 3)] = ll;
    }
}

// ---------------------------------------------------------------------------
// Launch
// ---------------------------------------------------------------------------
extern "C" void kernel_launch(void* const* d_in, const int* in_sizes, int n_in,
                              void* d_out, int out_size)
{
    const float* x      = (const float*)d_in[0];
    const float* w_attn = (const float*)d_in[1];
    const float* b_attn = (const float*)d_in[2];
    const float* w_proj = (const float*)d_in[3];
    const float* b_proj = (const float*)d_in[4];
    float* out = (float*)d_out;

    __half *xhi, *xlo, *wahi, *walo, *wphi, *wplo, *qkvhi, *qkvlo, *yhi, *ylo;
    cudaGetSymbolAddress((void**)&xhi,   g_xhi);
    cudaGetSymbolAddress((void**)&xlo,   g_xlo);
    cudaGetSymbolAddress((void**)&wahi,  g_wahi);
    cudaGetSymbolAddress((void**)&walo,  g_walo);
    cudaGetSymbolAddress((void**)&wphi,  g_wphi);
    cudaGetSymbolAddress((void**)&wplo,  g_wplo);
    cudaGetSymbolAddress((void**)&qkvhi, g_qkvhi);
    cudaGetSymbolAddress((void**)&qkvlo, g_qkvlo);
    cudaGetSymbolAddress((void**)&yhi,   g_yhi);
    cudaGetSymbolAddress((void**)&ylo,   g_ylo);

    cudaFuncSetAttribute(gemm_h_kernel,
                         cudaFuncAttributeMaxDynamicSharedMemorySize,
                         GEMM_SMEM_BYTES);
    cudaFuncSetAttribute(attn_tc_kernel,
                         cudaFuncAttributeMaxDynamicSharedMemorySize,
                         ATTN_TC_SMEM);

    convert_x_kernel<<<(M_ * C_ / 4 + 255) / 256, 256>>>(x, xhi, xlo, M_ * C_ / 4);
    convert_wT_kernel<<<dim3(W3_ / 32, C_ / 32), 256>>>(w_attn, wahi, walo, C_, W3_);
    convert_wT_kernel<<<dim3(C_ / 32, C_ / 32), 256>>>(w_proj, wphi, wplo, C_, C_);

    // qkv = x @ w_attn + b_attn -> split halves (3-term: feeds softmax)
    gemm_h_kernel<<<dim3(W3_ / 128, M_ / 128), 256, GEMM_SMEM_BYTES>>>(
        xhi, xlo, wahi, walo, b_attn, nullptr, qkvhi, qkvlo, 1, 1, M_, C_, W3_);

    // y = causal_attention(q, k, v) -> split halves
    attn_tc_kernel<<<dim3(T_ / 128, H_, B_), 256, ATTN_TC_SMEM>>>(
        qkvhi, qkvlo, yhi, ylo);

    // out = y @ w_proj + b_proj (fp32; 2-term — error budget allows)
    gemm_h_kernel<<<dim3(C_ / 128, M_ / 128), 256, GEMM_SMEM_BYTES>>>(
        yhi, ylo, wphi, wplo, b_proj, out, nullptr, nullptr, 0, 0, M_, C_, C_);
}

// round 14
// speedup vs baseline: 1.0508x; 1.0508x over previous
#include <cuda_runtime.h>
#include <cuda_fp16.h>
#include <cstdint>

// Problem constants
#define B_  4
#define T_  2048
#define C_  1024
#define H_  16
#define D_  64
#define M_  (B_ * T_)      // 8192 rows
#define W3_ (3 * C_)       // 3072

// Scratch (allocation-free rule: __device__ globals), all pre-split half data
__device__ __half g_xhi[(size_t)M_ * C_];
__device__ __half g_xlo[(size_t)M_ * C_];
__device__ __half g_wahi[(size_t)W3_ * C_];   // w_attn transposed [N][K]
__device__ __half g_walo[(size_t)W3_ * C_];
__device__ __half g_wphi[(size_t)C_ * C_];    // w_proj transposed [N][K]
__device__ __half g_wplo[(size_t)C_ * C_];
__device__ __half g_qkvhi[(size_t)M_ * W3_];
__device__ __half g_qkvlo[(size_t)M_ * W3_];
__device__ __half g_yhi[(size_t)M_ * C_];
__device__ __half g_ylo[(size_t)M_ * C_];

// ---------------------------------------------------------------------------
// helpers
// ---------------------------------------------------------------------------
__device__ __forceinline__ void mma_f16(float* acc, const uint32_t* a,
                                        const uint32_t* b) {
    asm volatile(
        "mma.sync.aligned.m16n8k16.row.col.f32.f16.f16.f32 "
        "{%0,%1,%2,%3}, {%4,%5,%6,%7}, {%8,%9}, {%0,%1,%2,%3};"
        : "+f"(acc[0]), "+f"(acc[1]), "+f"(acc[2]), "+f"(acc[3])
        : "r"(a[0]), "r"(a[1]), "r"(a[2]), "r"(a[3]),
          "r"(b[0]), "r"(b[1]));
}

__device__ __forceinline__ void split2(float x, float y, __half2& hi, __half2& lo) {
    hi = __float22half2_rn(make_float2(x, y));
    float2 h = __half22float2(hi);
    lo = __float22half2_rn(make_float2(x - h.x, y - h.y));
}

__device__ __forceinline__ uint32_t h2u(__half2 v) { return *(uint32_t*)&v; }

__device__ __forceinline__ float ex2f(float x) {
    float y;
    asm("ex2.approx.f32 %0, %1;" : "=f"(y) : "f"(x));
    return y;
}

__device__ __forceinline__ uint32_t smem_u32(const void* p) {
    uint32_t a;
    asm("{ .reg .u64 t; cvta.to.shared.u64 t, %1; cvt.u32.u64 %0, t; }"
        : "=r"(a) : "l"(p));
    return a;
}

__device__ __forceinline__ void ldsm_x4(uint32_t* r, uint32_t addr) {
    asm volatile("ldmatrix.sync.aligned.m8n8.x4.shared.b16 {%0,%1,%2,%3}, [%4];"
                 : "=r"(r[0]), "=r"(r[1]), "=r"(r[2]), "=r"(r[3]) : "r"(addr));
}
__device__ __forceinline__ void ldsm_x4_t(uint32_t* r, uint32_t addr) {
    asm volatile("ldmatrix.sync.aligned.m8n8.x4.trans.shared.b16 {%0,%1,%2,%3}, [%4];"
                 : "=r"(r[0]), "=r"(r[1]), "=r"(r[2]), "=r"(r[3]) : "r"(addr));
}

__device__ __forceinline__ void cp16(uint32_t saddr, const void* gptr) {
    asm volatile("cp.async.cg.shared.global [%0], [%1], 16;"
                 :: "r"(saddr), "l"(gptr) : "memory");
}
#define CP_COMMIT() asm volatile("cp.async.commit_group;" ::: "memory")
#define CP_WAIT(n)  asm volatile("cp.async.wait_group %0;" :: "n"(n) : "memory")

// ---------------------------------------------------------------------------
// Converter kernels
// ---------------------------------------------------------------------------
__global__ void __launch_bounds__(256) convert_x_kernel(
    const float* __restrict__ x, __half* __restrict__ xhi,
    __half* __restrict__ xlo, int n4)
{
    int i = blockIdx.x * 256 + threadIdx.x;
    if (i >= n4) return;
    float4 v = *(const float4*)(x + 4 * (size_t)i);
    __half2 h01, l01, h23, l23;
    split2(v.x, v.y, h01, l01);
    split2(v.z, v.w, h23, l23);
    *(__half2*)&xhi[4 * (size_t)i]     = h01;
    *(__half2*)&xhi[4 * (size_t)i + 2] = h23;
    *(__half2*)&xlo[4 * (size_t)i]     = l01;
    *(__half2*)&xlo[4 * (size_t)i + 2] = l23;
}

// W [K][N] fp32 -> Whi/Wlo [N][K] halves (transpose + split)
__global__ void __launch_bounds__(256) convert_wT_kernel(
    const float* __restrict__ W, __half* __restrict__ whi,
    __half* __restrict__ wlo, int K, int N)
{
    __shared__ float tile[32][33];
    const int tx = threadIdx.x & 31;
    const int ty = threadIdx.x >> 5;
    const int n0 = blockIdx.x * 32;
    const int k0 = blockIdx.y * 32;
    #pragma unroll
    for (int i = ty; i < 32; i += 8)
        tile[i][tx] = W[(size_t)(k0 + i) * N + n0 + tx];
    __syncthreads();
    #pragma unroll
    for (int i = ty; i < 32; i += 8) {
        float v = tile[tx][i];
        __half h = __float2half_rn(v);
        __half l = __float2half_rn(v - __half2float(h));
        whi[(size_t)(n0 + i) * K + k0 + tx] = h;
        wlo[(size_t)(n0 + i) * K + k0 + tx] = l;
    }
}

// ---------------------------------------------------------------------------
// Split-fp16 tensor GEMM, templated on THREE_TERM (no runtime branch).
// THREE_TERM=1: hh+hl+lh. THREE_TERM=0: hh+lh (B-lo never touched).
// 128x128 CTA tile, BK=32, 256 threads (8 warps 4Mx2N), cp.async pipeline.
// ---------------------------------------------------------------------------
#define APITCH 40
#define ST_ALO 10240
#define ST_BHI 20480
#define ST_BLO 30720
#define STAGE_B 40960
#define GEMM_SMEM_BYTES (2 * STAGE_B)     // 81920

template <int THREE_TERM, int WRITE_SPLIT>
__global__ void __launch_bounds__(256, 2) gemm_h_kernel(
    const __half* __restrict__ Ahi_g, const __half* __restrict__ Alo_g,
    const __half* __restrict__ Bhi_g, const __half* __restrict__ Blo_g,
    const float* __restrict__ bias,
    float* __restrict__ Out, __half* __restrict__ Ohi, __half* __restrict__ Olo,
    int M, int K, int N)
{
    extern __shared__ __half smh[];

    const int tid  = threadIdx.x;
    const int w    = tid >> 5;
    const int lane = tid & 31;
    const int g    = lane >> 2;
    const int tig  = lane & 3;
    const int wm   = (w & 3) * 32;
    const int wn   = (w >> 2) * 64;

    const int lrow16 = lane & 15;
    const int lhi8   = (lane & 16) >> 1;
    const int l8     = lane & 8;

    const int bm = blockIdx.y * 128;
    const int bn = blockIdx.x * 128;

    const int sr = tid >> 2;          // 0..63 (+64)
    const int sc = tid & 3;           // 16B chunk within row

    const uint32_t sbase = smem_u32(smh);

    float acc[2][8][4] = {};

    const int nchunk = K >> 5;

    const __half* gA  = Ahi_g + (size_t)(bm + sr) * K + 8 * sc;
    const __half* gAl = Alo_g + (size_t)(bm + sr) * K + 8 * sc;
    const __half* gB  = Bhi_g + (size_t)(bn + sr) * K + 8 * sc;
    const __half* gBl = Blo_g + (size_t)(bn + sr) * K + 8 * sc;
    const size_t rstep = 64 * (size_t)K;

    auto issue = [&](int c, int buf) {
        const int k0 = c << 5;
        const uint32_t S = sbase + (buf ? STAGE_B : 0);
        #pragma unroll
        for (int l = 0; l < 2; l++) {
            const uint32_t off = (uint32_t)(sr + 64 * l) * 80 + 16 * sc;
            cp16(S + off,          gA  + l * rstep + k0);
            cp16(S + ST_ALO + off, gAl + l * rstep + k0);
            cp16(S + ST_BHI + off, gB  + l * rstep + k0);
            if (THREE_TERM)
                cp16(S + ST_BLO + off, gBl + l * rstep + k0);
        }
        CP_COMMIT();
    };

    issue(0, 0);

    for (int c = 0; c < nchunk; c++) {
        CP_WAIT(0);
        __syncthreads();
        if (c + 1 < nchunk) issue(c + 1, (c + 1) & 1);

        const uint32_t sA = sbase + ((c & 1) ? STAGE_B : 0);

        #pragma unroll
        for (int ks = 0; ks < 2; ks++) {
            uint32_t ah[2][4], al[2][4];
            #pragma unroll
            for (int ti = 0; ti < 2; ti++) {
                const uint32_t aoff =
                    2 * ((wm + (ti << 4) + lrow16) * APITCH + (ks << 4) + lhi8);
                ldsm_x4(ah[ti], sA + aoff);
                ldsm_x4(al[ti], sA + ST_ALO + aoff);
            }
            #pragma unroll
            for (int jp = 0; jp < 4; jp++) {
                const uint32_t boff =
                    2 * ((wn + (jp << 4) + (lane & 7) + lhi8) * APITCH + (ks << 4) + l8);
                uint32_t bh[4], bl[4];
                ldsm_x4(bh, sA + ST_BHI + boff);
                if (THREE_TERM) ldsm_x4(bl, sA + ST_BLO + boff);
                // term-major ordering: same-acc distance = 4
                mma_f16(acc[0][2 * jp],     ah[0], bh);
                mma_f16(acc[0][2 * jp + 1], ah[0], bh + 2);
                mma_f16(acc[1][2 * jp],     ah[1], bh);
                mma_f16(acc[1][2 * jp + 1], ah[1], bh + 2);
                if (THREE_TERM) {
                    mma_f16(acc[0][2 * jp],     ah[0], bl);
                    mma_f16(acc[0][2 * jp + 1], ah[0], bl + 2);
                    mma_f16(acc[1][2 * jp],     ah[1], bl);
                    mma_f16(acc[1][2 * jp + 1], ah[1], bl + 2);
                }
                mma_f16(acc[0][2 * jp],     al[0], bh);
                mma_f16(acc[0][2 * jp + 1], al[0], bh + 2);
                mma_f16(acc[1][2 * jp],     al[1], bh);
                mma_f16(acc[1][2 * jp + 1], al[1], bh + 2);
            }
        }
    }

    // ---- epilogue ----
    if (WRITE_SPLIT) {
        #pragma unroll
        for (int j = 0; j < 8; j++) {
            const int col = bn + wn + (j << 3) + (tig << 1);
            const float2 bb = *(const float2*)(bias + col);
            #pragma unroll
            for (int ti = 0; ti < 2; ti++) {
                const int row = bm + wm + (ti << 4) + g;
                __half2 hh, ll;
                split2(acc[ti][j][0] + bb.x, acc[ti][j][1] + bb.y, hh, ll);
                *(__half2*)&Ohi[(size_t)row * N + col] = hh;
                *(__half2*)&Olo[(size_t)row * N + col] = ll;
                split2(acc[ti][j][2] + bb.x, acc[ti][j][3] + bb.y, hh, ll);
                *(__half2*)&Ohi[(size_t)(row + 8) * N + col] = hh;
                *(__half2*)&Olo[(size_t)(row + 8) * N + col] = ll;
            }
        }
    } else {
        #pragma unroll
        for (int j = 0; j < 8; j++) {
            const int col = bn + wn + (j << 3) + (tig << 1);
            const float2 bb = *(const float2*)(bias + col);
            #pragma unroll
            for (int ti = 0; ti < 2; ti++) {
                const int row = bm + wm + (ti << 4) + g;
                float2 o0, o1;
                o0.x = acc[ti][j][0] + bb.x;
                o0.y = acc[ti][j][1] + bb.y;
                o1.x = acc[ti][j][2] + bb.x;
                o1.y = acc[ti][j][3] + bb.y;
                *(float2*)(Out + (size_t)row * N + col)       = o0;
                *(float2*)(Out + (size_t)(row + 8) * N + col) = o1;
            }
        }
    }
}

// ---------------------------------------------------------------------------
// Split-fp16 TC causal flash attention.
// exp2-domain softmax (scale = 8*log2e), single masked path (R12 schedule),
// qi reversal for causal load balance.
// ---------------------------------------------------------------------------
#define KPITCH 72
#define KV_STAGE 36864
#define AK_LO_B (64 * KPITCH * 2)
#define AV_HI_B (2 * 64 * KPITCH * 2)
#define AV_LO_B (3 * 64 * KPITCH * 2)
#define AQ_LO_B (128 * KPITCH * 2)
#define KV_BASE 36864
#define ATTN_TC_SMEM (KV_BASE + 2 * KV_STAGE)   // 110592
#define SM_SCALE 11.5415603f                     // 8 * log2(e)

__global__ void __launch_bounds__(256, 2) attn_tc_kernel(
    const __half* __restrict__ qkvhi, const __half* __restrict__ qkvlo,
    __half* __restrict__ yhi, __half* __restrict__ ylo)
{
    extern __shared__ __half sha[];

    const int tid  = threadIdx.x;
    const int w    = tid >> 5;
    const int lane = tid & 31;
    const int g    = lane >> 2;
    const int tig  = lane & 3;
    const int lrow16 = lane & 15;
    const int lhi8   = (lane & 16) >> 1;
    const int l8     = lane & 8;
    const int qi   = gridDim.x - 1 - blockIdx.x;   // heaviest CTAs first
    const int h    = blockIdx.y;
    const int b    = blockIdx.z;
    const int qblock = qi * 128;

    const uint32_t sbase = smem_u32(sha);
    const size_t rowbase = (size_t)b * T_ * W3_ + h * D_;

    const int sr = tid >> 3;
    const int sc = tid & 7;

    auto issue_kv = [&](int kj, int buf) {
        const uint32_t S = sbase + KV_BASE + (buf ? KV_STAGE : 0);
        #pragma unroll
        for (int l = 0; l < 2; l++) {
            const int r = sr + 32 * l;
            const size_t src = rowbase + (size_t)(kj * 64 + r) * W3_ + 8 * sc;
            const uint32_t off = (uint32_t)r * 144 + 16 * sc;
            cp16(S + off,           qkvhi + src + C_);
            cp16(S + AK_LO_B + off, qkvlo + src + C_);
            cp16(S + AV_HI_B + off, qkvhi + src + 2 * C_);
            cp16(S + AV_LO_B + off, qkvlo + src + 2 * C_);
        }
        CP_COMMIT();
    };

    issue_kv(0, 0);

    {
        char* S = (char*)sha;
        #pragma unroll
        for (int l = 0; l < 4; l++) {
            const int r = sr + 32 * l;
            const size_t src = rowbase + (size_t)(qblock + r) * W3_ + 8 * sc;
            const int off = r * 144 + 16 * sc;
            *(uint4*)(S + off)           = *(const uint4*)(qkvhi + src);
            *(uint4*)(S + AQ_LO_B + off) = *(const uint4*)(qkvlo + src);
        }
    }
    __syncthreads();

    uint32_t qh[4][4], ql[4][4];
    #pragma unroll
    for (int kc = 0; kc < 4; kc++) {
        const uint32_t qoff = 2 * (((w << 4) + lrow16) * KPITCH + (kc << 4) + lhi8);
        ldsm_x4(qh[kc], sbase + qoff);
        ldsm_x4(ql[kc], sbase + AQ_LO_B + qoff);
    }

    const int row0 = qblock + (w << 4) + g;
    const int row1 = row0 + 8;

    float m0 = -1e30f, m1 = -1e30f, l0 = 0.0f, l1 = 0.0f;
    float o[8][4] = {};

    const int nkj = 2 * qi + 2;

    for (int kj = 0; kj < nkj; kj++) {
        CP_WAIT(0);
        __syncthreads();
        if (kj + 1 < nkj) issue_kv(kj + 1, (kj + 1) & 1);

        const uint32_t sKV = sbase + KV_BASE + ((kj & 1) ? KV_STAGE : 0);

        // ---- S = Q @ K^T ----
        float sacc[8][4] = {};
        #pragma unroll
        for (int kc = 0; kc < 4; kc++) {
            #pragma unroll
            for (int jnp = 0; jnp < 4; jnp++) {
                const uint32_t koff =
                    2 * (((jnp << 4) + (lane & 7) + lhi8) * KPITCH + (kc << 4) + l8);
                uint32_t kh[4], kl[4];
                ldsm_x4(kh, sKV + koff);
                ldsm_x4(kl, sKV + AK_LO_B + koff);
                mma_f16(sacc[2 * jnp],     qh[kc], kh);
                mma_f16(sacc[2 * jnp + 1], qh[kc], kh + 2);
                mma_f16(sacc[2 * jnp],     qh[kc], kl);
                mma_f16(sacc[2 * jnp + 1], qh[kc], kl + 2);
                mma_f16(sacc[2 * jnp],     ql[kc], kh);
                mma_f16(sacc[2 * jnp + 1], ql[kc], kh + 2);
            }
        }

        // ---- mask + scale (exp2 domain) + online softmax ----
        float tm0 = -1e30f, tm1 = -1e30f;
        #pragma unroll
        for (int jn = 0; jn < 8; jn++) {
            const int c0 = kj * 64 + (jn << 3) + (tig << 1);
            float v0 = (c0     <= row0) ? sacc[jn][0] * SM_SCALE : -1e30f;
            float v1 = (c0 + 1 <= row0) ? sacc[jn][1] * SM_SCALE : -1e30f;
            float v2 = (c0     <= row1) ? sacc[jn][2] * SM_SCALE : -1e30f;
            float v3 = (c0 + 1 <= row1) ? sacc[jn][3] * SM_SCALE : -1e30f;
            sacc[jn][0] = v0; sacc[jn][1] = v1;
            sacc[jn][2] = v2; sacc[jn][3] = v3;
            tm0 = fmaxf(tm0, fmaxf(v0, v1));
            tm1 = fmaxf(tm1, fmaxf(v2, v3));
        }
        tm0 = fmaxf(tm0, __shfl_xor_sync(0xffffffffu, tm0, 1));
        tm0 = fmaxf(tm0, __shfl_xor_sync(0xffffffffu, tm0, 2));
        tm1 = fmaxf(tm1, __shfl_xor_sync(0xffffffffu, tm1, 1));
        tm1 = fmaxf(tm1, __shfl_xor_sync(0xffffffffu, tm1, 2));

        const float mn0 = fmaxf(m0, tm0);
        const float mn1 = fmaxf(m1, tm1);
        const float al0 = ex2f(m0 - mn0);
        const float al1 = ex2f(m1 - mn1);
        m0 = mn0; m1 = mn1;

        float s0 = 0.0f, s1 = 0.0f;
        #pragma unroll
        for (int jn = 0; jn < 8; jn++) {
            float p0 = ex2f(sacc[jn][0] - mn0);
            float p1 = ex2f(sacc[jn][1] - mn0);
            float p2 = ex2f(sacc[jn][2] - mn1);
            float p3 = ex2f(sacc[jn][3] - mn1);
            sacc[jn][0] = p0; sacc[jn][1] = p1;
            sacc[jn][2] = p2; sacc[jn][3] = p3;
            s0 += p0 + p1;
            s1 += p2 + p3;
        }
        s0 += __shfl_xor_sync(0xffffffffu, s0, 1);
        s0 += __shfl_xor_sync(0xffffffffu, s0, 2);
        s1 += __shfl_xor_sync(0xffffffffu, s1, 1);
        s1 += __shfl_xor_sync(0xffffffffu, s1, 2);
        l0 = l0 * al0 + s0;
        l1 = l1 * al1 + s1;

        // ---- rescale O, then O += P @ V ----
        #pragma unroll
        for (int jd = 0; jd < 8; jd++) {
            o[jd][0] *= al0; o[jd][1] *= al0;
            o[jd][2] *= al1; o[jd][3] *= al1;
        }

        #pragma unroll
        for (int kc = 0; kc < 4; kc++) {
            uint32_t ph[4], pl[4];
            {
                __half2 hh, ll;
                split2(sacc[2 * kc][0], sacc[2 * kc][1], hh, ll);
                ph[0] = h2u(hh); pl[0] = h2u(ll);
                split2(sacc[2 * kc][2], sacc[2 * kc][3], hh, ll);
                ph[1] = h2u(hh); pl[1] = h2u(ll);
                split2(sacc[2 * kc + 1][0], sacc[2 * kc + 1][1], hh, ll);
                ph[2] = h2u(hh); pl[2] = h2u(ll);
                split2(sacc[2 * kc + 1][2], sacc[2 * kc + 1][3], hh, ll);
                ph[3] = h2u(hh); pl[3] = h2u(ll);
            }
            #pragma unroll
            for (int jdp = 0; jdp < 4; jdp++) {
                const uint32_t voff =
                    2 * (((kc << 4) + lrow16) * KPITCH + (jdp << 4) + lhi8);
                uint32_t vh[4], vl[4];
                ldsm_x4_t(vh, sKV + AV_HI_B + voff);
                ldsm_x4_t(vl, sKV + AV_LO_B + voff);
                mma_f16(o[2 * jdp],     ph, vh);
                mma_f16(o[2 * jdp + 1], ph, vh + 2);
                mma_f16(o[2 * jdp],     ph, vl);
                mma_f16(o[2 * jdp + 1], ph, vl + 2);
                mma_f16(o[2 * jdp],     pl, vh);
                mma_f16(o[2 * jdp + 1], pl, vh + 2);
            }
        }
    }

    const float inv0 = 1.0f / l0;
    const float inv1 = 1.0f / l1;
    const size_t y0 = (size_t)(b * T_ + row0) * C_ + h * D_ + (tig << 1);
    const size_t y1 = y0 + 8 * (size_t)C_;
    #pragma unroll
    for (int jd = 0; jd < 8; jd++) {
        __half2 hh, ll;
        split2(o[jd][0] * inv0, o[jd][1] * inv0, hh, ll);
        *(__half2*)&yhi[y0 + (jd << 3)] = hh;
        *(__half2*)&ylo[y0 + (jd << 3)] = ll;
        split2(o[jd][2] * inv1, o[jd][3] * inv1, hh, ll);
        *(__half2*)&yhi[y1 + (jd << 3)] = hh;
        *(__half2*)&ylo[y1 + (jd << 3)] = ll;
    }
}

// ---------------------------------------------------------------------------
// Launch
// ---------------------------------------------------------------------------
extern "C" void kernel_launch(void* const* d_in, const int* in_sizes, int n_in,
                              void* d_out, int out_size)
{
    const float* x      = (const float*)d_in[0];
    const float* w_attn = (const float*)d_in[1];
    const float* b_attn = (const float*)d_in[2];
    const float* w_proj = (const float*)d_in[3];
    const float* b_proj = (const float*)d_in[4];
    float* out = (float*)d_out;

    __half *xhi, *xlo, *wahi, *walo, *wphi, *wplo, *qkvhi, *qkvlo, *yhi, *ylo;
    cudaGetSymbolAddress((void**)&xhi,   g_xhi);
    cudaGetSymbolAddress((void**)&xlo,   g_xlo);
    cudaGetSymbolAddress((void**)&wahi,  g_wahi);
    cudaGetSymbolAddress((void**)&walo,  g_walo);
    cudaGetSymbolAddress((void**)&wphi,  g_wphi);
    cudaGetSymbolAddress((void**)&wplo,  g_wplo);
    cudaGetSymbolAddress((void**)&qkvhi, g_qkvhi);
    cudaGetSymbolAddress((void**)&qkvlo, g_qkvlo);
    cudaGetSymbolAddress((void**)&yhi,   g_yhi);
    cudaGetSymbolAddress((void**)&ylo,   g_ylo);

    cudaFuncSetAttribute(gemm_h_kernel<1, 1>,
                         cudaFuncAttributeMaxDynamicSharedMemorySize,
                         GEMM_SMEM_BYTES);
    cudaFuncSetAttribute(gemm_h_kernel<0, 0>,
                         cudaFuncAttributeMaxDynamicSharedMemorySize,
                         GEMM_SMEM_BYTES);
    cudaFuncSetAttribute(attn_tc_kernel,
                         cudaFuncAttributeMaxDynamicSharedMemorySize,
                         ATTN_TC_SMEM);

    convert_x_kernel<<<(M_ * C_ / 4 + 255) / 256, 256>>>(x, xhi, xlo, M_ * C_ / 4);
    convert_wT_kernel<<<dim3(W3_ / 32, C_ / 32), 256>>>(w_attn, wahi, walo, C_, W3_);
    convert_wT_kernel<<<dim3(C_ / 32, C_ / 32), 256>>>(w_proj, wphi, wplo, C_, C_);

    // qkv = x @ w_attn + b_attn -> split halves (3-term: feeds softmax)
    gemm_h_kernel<1, 1><<<dim3(W3_ / 128, M_ / 128), 256, GEMM_SMEM_BYTES>>>(
        xhi, xlo, wahi, walo, b_attn, nullptr, qkvhi, qkvlo, M_, C_, W3_);

    // y = causal_attention(q, k, v) -> split halves
    attn_tc_kernel<<<dim3(T_ / 128, H_, B_), 256, ATTN_TC_SMEM>>>(
        qkvhi, qkvlo, yhi, ylo);

    // out = y @ w_proj + b_proj (fp32; 2-term — error budget allows)
    gemm_h_kernel<0, 0><<<dim3(C_ / 128, M_ / 128), 256, GEMM_SMEM_BYTES>>>(
        yhi, ylo, wphi, wplo, b_proj, out, nullptr, nullptr, M_, C_, C_);
}

// round 15
// speedup vs baseline: 1.0934x; 1.0405x over previous
#include <cuda_runtime.h>
#include <cuda_fp16.h>
#include <cstdint>

// Problem constants
#define B_  4
#define T_  2048
#define C_  1024
#define H_  16
#define D_  64
#define M_  (B_ * T_)      // 8192 rows
#define W3_ (3 * C_)       // 3072

// Scratch (allocation-free rule: __device__ globals), all pre-split half data
__device__ __half g_xhi[(size_t)M_ * C_];
__device__ __half g_xlo[(size_t)M_ * C_];
__device__ __half g_wahi[(size_t)W3_ * C_];   // w_attn transposed [N][K]
__device__ __half g_walo[(size_t)W3_ * C_];
__device__ __half g_wphi[(size_t)C_ * C_];    // w_proj transposed [N][K]
__device__ __half g_wplo[(size_t)C_ * C_];
__device__ __half g_qkvhi[(size_t)M_ * W3_];
__device__ __half g_qkvlo[(size_t)M_ * W3_];
__device__ __half g_yhi[(size_t)M_ * C_];
__device__ __half g_ylo[(size_t)M_ * C_];

// ---------------------------------------------------------------------------
// helpers
// ---------------------------------------------------------------------------
__device__ __forceinline__ void mma_f16(float* acc, const uint32_t* a,
                                        const uint32_t* b) {
    asm volatile(
        "mma.sync.aligned.m16n8k16.row.col.f32.f16.f16.f32 "
        "{%0,%1,%2,%3}, {%4,%5,%6,%7}, {%8,%9}, {%0,%1,%2,%3};"
        : "+f"(acc[0]), "+f"(acc[1]), "+f"(acc[2]), "+f"(acc[3])
        : "r"(a[0]), "r"(a[1]), "r"(a[2]), "r"(a[3]),
          "r"(b[0]), "r"(b[1]));
}

__device__ __forceinline__ void split2(float x, float y, __half2& hi, __half2& lo) {
    hi = __float22half2_rn(make_float2(x, y));
    float2 h = __half22float2(hi);
    lo = __float22half2_rn(make_float2(x - h.x, y - h.y));
}

__device__ __forceinline__ uint32_t h2u(__half2 v) { return *(uint32_t*)&v; }

__device__ __forceinline__ float ex2f(float x) {
    float y;
    asm("ex2.approx.f32 %0, %1;" : "=f"(y) : "f"(x));
    return y;
}

__device__ __forceinline__ uint32_t smem_u32(const void* p) {
    uint32_t a;
    asm("{ .reg .u64 t; cvta.to.shared.u64 t, %1; cvt.u32.u64 %0, t; }"
        : "=r"(a) : "l"(p));
    return a;
}

__device__ __forceinline__ void ldsm_x4(uint32_t* r, uint32_t addr) {
    asm volatile("ldmatrix.sync.aligned.m8n8.x4.shared.b16 {%0,%1,%2,%3}, [%4];"
                 : "=r"(r[0]), "=r"(r[1]), "=r"(r[2]), "=r"(r[3]) : "r"(addr));
}
__device__ __forceinline__ void ldsm_x4_t(uint32_t* r, uint32_t addr) {
    asm volatile("ldmatrix.sync.aligned.m8n8.x4.trans.shared.b16 {%0,%1,%2,%3}, [%4];"
                 : "=r"(r[0]), "=r"(r[1]), "=r"(r[2]), "=r"(r[3]) : "r"(addr));
}

__device__ __forceinline__ void cp16(uint32_t saddr, const void* gptr) {
    asm volatile("cp.async.cg.shared.global [%0], [%1], 16;"
                 :: "r"(saddr), "l"(gptr) : "memory");
}
#define CP_COMMIT() asm volatile("cp.async.commit_group;" ::: "memory")
#define CP_WAIT(n)  asm volatile("cp.async.wait_group %0;" :: "n"(n) : "memory")

// ---------------------------------------------------------------------------
// Converter kernels
// ---------------------------------------------------------------------------
__global__ void __launch_bounds__(256) convert_x_kernel(
    const float* __restrict__ x, __half* __restrict__ xhi,
    __half* __restrict__ xlo, int n4)
{
    int i = blockIdx.x * 256 + threadIdx.x;
    if (i >= n4) return;
    float4 v = *(const float4*)(x + 4 * (size_t)i);
    __half2 h01, l01, h23, l23;
    split2(v.x, v.y, h01, l01);
    split2(v.z, v.w, h23, l23);
    *(__half2*)&xhi[4 * (size_t)i]     = h01;
    *(__half2*)&xhi[4 * (size_t)i + 2] = h23;
    *(__half2*)&xlo[4 * (size_t)i]     = l01;
    *(__half2*)&xlo[4 * (size_t)i + 2] = l23;
}

// W [K][N] fp32 -> Whi/Wlo [N][K] halves (transpose + split)
__global__ void __launch_bounds__(256) convert_wT_kernel(
    const float* __restrict__ W, __half* __restrict__ whi,
    __half* __restrict__ wlo, int K, int N)
{
    __shared__ float tile[32][33];
    const int tx = threadIdx.x & 31;
    const int ty = threadIdx.x >> 5;
    const int n0 = blockIdx.x * 32;
    const int k0 = blockIdx.y * 32;
    #pragma unroll
    for (int i = ty; i < 32; i += 8)
        tile[i][tx] = W[(size_t)(k0 + i) * N + n0 + tx];
    __syncthreads();
    #pragma unroll
    for (int i = ty; i < 32; i += 8) {
        float v = tile[tx][i];
        __half h = __float2half_rn(v);
        __half l = __float2half_rn(v - __half2float(h));
        whi[(size_t)(n0 + i) * K + k0 + tx] = h;
        wlo[(size_t)(n0 + i) * K + k0 + tx] = l;
    }
}

// ---------------------------------------------------------------------------
// Split-fp16 tensor GEMM, templated on THREE_TERM (no runtime branch).
// THREE_TERM=1: hh+hl+lh. THREE_TERM=0: hh+lh (B-lo never touched).
// 128x128 CTA tile, BK=32, 256 threads (8 warps 4Mx2N), cp.async pipeline.
// ---------------------------------------------------------------------------
#define APITCH 40
#define ST_ALO 10240
#define ST_BHI 20480
#define ST_BLO 30720
#define STAGE_B 40960
#define GEMM_SMEM_BYTES (2 * STAGE_B)     // 81920

template <int THREE_TERM, int WRITE_SPLIT>
__global__ void __launch_bounds__(256, 2) gemm_h_kernel(
    const __half* __restrict__ Ahi_g, const __half* __restrict__ Alo_g,
    const __half* __restrict__ Bhi_g, const __half* __restrict__ Blo_g,
    const float* __restrict__ bias,
    float* __restrict__ Out, __half* __restrict__ Ohi, __half* __restrict__ Olo,
    int M, int K, int N)
{
    extern __shared__ __half smh[];

    const int tid  = threadIdx.x;
    const int w    = tid >> 5;
    const int lane = tid & 31;
    const int g    = lane >> 2;
    const int tig  = lane & 3;
    const int wm   = (w & 3) * 32;
    const int wn   = (w >> 2) * 64;

    const int lrow16 = lane & 15;
    const int lhi8   = (lane & 16) >> 1;
    const int l8     = lane & 8;

    const int bm = blockIdx.y * 128;
    const int bn = blockIdx.x * 128;

    const int sr = tid >> 2;          // 0..63 (+64)
    const int sc = tid & 3;           // 16B chunk within row

    const uint32_t sbase = smem_u32(smh);

    float acc[2][8][4] = {};

    const int nchunk = K >> 5;

    const __half* gA  = Ahi_g + (size_t)(bm + sr) * K + 8 * sc;
    const __half* gAl = Alo_g + (size_t)(bm + sr) * K + 8 * sc;
    const __half* gB  = Bhi_g + (size_t)(bn + sr) * K + 8 * sc;
    const __half* gBl = Blo_g + (size_t)(bn + sr) * K + 8 * sc;
    const size_t rstep = 64 * (size_t)K;

    auto issue = [&](int c, int buf) {
        const int k0 = c << 5;
        const uint32_t S = sbase + (buf ? STAGE_B : 0);
        #pragma unroll
        for (int l = 0; l < 2; l++) {
            const uint32_t off = (uint32_t)(sr + 64 * l) * 80 + 16 * sc;
            cp16(S + off,          gA  + l * rstep + k0);
            cp16(S + ST_ALO + off, gAl + l * rstep + k0);
            cp16(S + ST_BHI + off, gB  + l * rstep + k0);
            if (THREE_TERM)
                cp16(S + ST_BLO + off, gBl + l * rstep + k0);
        }
        CP_COMMIT();
    };

    issue(0, 0);

    for (int c = 0; c < nchunk; c++) {
        CP_WAIT(0);
        __syncthreads();
        if (c + 1 < nchunk) issue(c + 1, (c + 1) & 1);

        const uint32_t sA = sbase + ((c & 1) ? STAGE_B : 0);

        #pragma unroll
        for (int ks = 0; ks < 2; ks++) {
            uint32_t ah[2][4], al[2][4];
            #pragma unroll
            for (int ti = 0; ti < 2; ti++) {
                const uint32_t aoff =
                    2 * ((wm + (ti << 4) + lrow16) * APITCH + (ks << 4) + lhi8);
                ldsm_x4(ah[ti], sA + aoff);
                ldsm_x4(al[ti], sA + ST_ALO + aoff);
            }
            #pragma unroll
            for (int jp = 0; jp < 4; jp++) {
                const uint32_t boff =
                    2 * ((wn + (jp << 4) + (lane & 7) + lhi8) * APITCH + (ks << 4) + l8);
                uint32_t bh[4], bl[4];
                ldsm_x4(bh, sA + ST_BHI + boff);
                if (THREE_TERM) ldsm_x4(bl, sA + ST_BLO + boff);
                // term-major ordering: same-acc distance = 4
                mma_f16(acc[0][2 * jp],     ah[0], bh);
                mma_f16(acc[0][2 * jp + 1], ah[0], bh + 2);
                mma_f16(acc[1][2 * jp],     ah[1], bh);
                mma_f16(acc[1][2 * jp + 1], ah[1], bh + 2);
                if (THREE_TERM) {
                    mma_f16(acc[0][2 * jp],     ah[0], bl);
                    mma_f16(acc[0][2 * jp + 1], ah[0], bl + 2);
                    mma_f16(acc[1][2 * jp],     ah[1], bl);
                    mma_f16(acc[1][2 * jp + 1], ah[1], bl + 2);
                }
                mma_f16(acc[0][2 * jp],     al[0], bh);
                mma_f16(acc[0][2 * jp + 1], al[0], bh + 2);
                mma_f16(acc[1][2 * jp],     al[1], bh);
                mma_f16(acc[1][2 * jp + 1], al[1], bh + 2);
            }
        }
    }

    // ---- epilogue ----
    if (WRITE_SPLIT) {
        #pragma unroll
        for (int j = 0; j < 8; j++) {
            const int col = bn + wn + (j << 3) + (tig << 1);
            const float2 bb = *(const float2*)(bias + col);
            #pragma unroll
            for (int ti = 0; ti < 2; ti++) {
                const int row = bm + wm + (ti << 4) + g;
                __half2 hh, ll;
                split2(acc[ti][j][0] + bb.x, acc[ti][j][1] + bb.y, hh, ll);
                *(__half2*)&Ohi[(size_t)row * N + col] = hh;
                *(__half2*)&Olo[(size_t)row * N + col] = ll;
                split2(acc[ti][j][2] + bb.x, acc[ti][j][3] + bb.y, hh, ll);
                *(__half2*)&Ohi[(size_t)(row + 8) * N + col] = hh;
                *(__half2*)&Olo[(size_t)(row + 8) * N + col] = ll;
            }
        }
    } else {
        #pragma unroll
        for (int j = 0; j < 8; j++) {
            const int col = bn + wn + (j << 3) + (tig << 1);
            const float2 bb = *(const float2*)(bias + col);
            #pragma unroll
            for (int ti = 0; ti < 2; ti++) {
                const int row = bm + wm + (ti << 4) + g;
                float2 o0, o1;
                o0.x = acc[ti][j][0] + bb.x;
                o0.y = acc[ti][j][1] + bb.y;
                o1.x = acc[ti][j][2] + bb.x;
                o1.y = acc[ti][j][3] + bb.y;
                *(float2*)(Out + (size_t)row * N + col)       = o0;
                *(float2*)(Out + (size_t)(row + 8) * N + col) = o1;
            }
        }
    }
}

// ---------------------------------------------------------------------------
// Split-fp16 TC causal flash attention.
// exp2-domain softmax (scale = 8*log2e), single masked path,
// qi reversal for causal load balance.
// ---------------------------------------------------------------------------
#define KPITCH 72
#define KV_STAGE 36864
#define AK_LO_B (64 * KPITCH * 2)
#define AV_HI_B (2 * 64 * KPITCH * 2)
#define AV_LO_B (3 * 64 * KPITCH * 2)
#define AQ_LO_B (128 * KPITCH * 2)
#define KV_BASE 36864
#define ATTN_TC_SMEM (KV_BASE + 2 * KV_STAGE)   // 110592
#define SM_SCALE 11.5415603f                     // 8 * log2(e)

__global__ void __launch_bounds__(256, 2) attn_tc_kernel(
    const __half* __restrict__ qkvhi, const __half* __restrict__ qkvlo,
    __half* __restrict__ yhi, __half* __restrict__ ylo)
{
    extern __shared__ __half sha[];

    const int tid  = threadIdx.x;
    const int w    = tid >> 5;
    const int lane = tid & 31;
    const int g    = lane >> 2;
    const int tig  = lane & 3;
    const int lrow16 = lane & 15;
    const int lhi8   = (lane & 16) >> 1;
    const int l8     = lane & 8;
    const int qi   = gridDim.x - 1 - blockIdx.x;   // heaviest CTAs first
    const int h    = blockIdx.y;
    const int b    = blockIdx.z;
    const int qblock = qi * 128;

    const uint32_t sbase = smem_u32(sha);
    const size_t rowbase = (size_t)b * T_ * W3_ + h * D_;

    const int sr = tid >> 3;
    const int sc = tid & 7;

    auto issue_kv = [&](int kj, int buf) {
        const uint32_t S = sbase + KV_BASE + (buf ? KV_STAGE : 0);
        #pragma unroll
        for (int l = 0; l < 2; l++) {
            const int r = sr + 32 * l;
            const size_t src = rowbase + (size_t)(kj * 64 + r) * W3_ + 8 * sc;
            const uint32_t off = (uint32_t)r * 144 + 16 * sc;
            cp16(S + off,           qkvhi + src + C_);
            cp16(S + AK_LO_B + off, qkvlo + src + C_);
            cp16(S + AV_HI_B + off, qkvhi + src + 2 * C_);
            cp16(S + AV_LO_B + off, qkvlo + src + 2 * C_);
        }
        CP_COMMIT();
    };

    issue_kv(0, 0);

    {
        char* S = (char*)sha;
        #pragma unroll
        for (int l = 0; l < 4; l++) {
            const int r = sr + 32 * l;
            const size_t src = rowbase + (size_t)(qblock + r) * W3_ + 8 * sc;
            const int off = r * 144 + 16 * sc;
            *(uint4*)(S + off)           = *(const uint4*)(qkvhi + src);
            *(uint4*)(S + AQ_LO_B + off) = *(const uint4*)(qkvlo + src);
        }
    }
    __syncthreads();

    uint32_t qh[4][4], ql[4][4];
    #pragma unroll
    for (int kc = 0; kc < 4; kc++) {
        const uint32_t qoff = 2 * (((w << 4) + lrow16) * KPITCH + (kc << 4) + lhi8);
        ldsm_x4(qh[kc], sbase + qoff);
        ldsm_x4(ql[kc], sbase + AQ_LO_B + qoff);
    }

    const int row0 = qblock + (w << 4) + g;
    const int row1 = row0 + 8;

    float m0 = -1e30f, m1 = -1e30f, l0 = 0.0f, l1 = 0.0f;
    float o[8][4] = {};

    const int nkj = 2 * qi + 2;

    for (int kj = 0; kj < nkj; kj++) {
        CP_WAIT(0);
        __syncthreads();
        if (kj + 1 < nkj) issue_kv(kj + 1, (kj + 1) & 1);

        const uint32_t sKV = sbase + KV_BASE + ((kj & 1) ? KV_STAGE : 0);

        // ---- S = Q @ K^T ----
        float sacc[8][4] = {};
        #pragma unroll
        for (int kc = 0; kc < 4; kc++) {
            #pragma unroll
            for (int jnp = 0; jnp < 4; jnp++) {
                const uint32_t koff =
                    2 * (((jnp << 4) + (lane & 7) + lhi8) * KPITCH + (kc << 4) + l8);
                uint32_t kh[4], kl[4];
                ldsm_x4(kh, sKV + koff);
                ldsm_x4(kl, sKV + AK_LO_B + koff);
                mma_f16(sacc[2 * jnp],     qh[kc], kh);
                mma_f16(sacc[2 * jnp + 1], qh[kc], kh + 2);
                mma_f16(sacc[2 * jnp],     qh[kc], kl);
                mma_f16(sacc[2 * jnp + 1], qh[kc], kl + 2);
                mma_f16(sacc[2 * jnp],     ql[kc], kh);
                mma_f16(sacc[2 * jnp + 1], ql[kc], kh + 2);
            }
        }

        // ---- mask + scale (exp2 domain) + online softmax ----
        float tm0 = -1e30f, tm1 = -1e30f;
        #pragma unroll
        for (int jn = 0; jn < 8; jn++) {
            const int c0 = kj * 64 + (jn << 3) + (tig << 1);
            float v0 = (c0     <= row0) ? sacc[jn][0] * SM_SCALE : -1e30f;
            float v1 = (c0 + 1 <= row0) ? sacc[jn][1] * SM_SCALE : -1e30f;
            float v2 = (c0     <= row1) ? sacc[jn][2] * SM_SCALE : -1e30f;
            float v3 = (c0 + 1 <= row1) ? sacc[jn][3] * SM_SCALE : -1e30f;
            sacc[jn][0] = v0; sacc[jn][1] = v1;
            sacc[jn][2] = v2; sacc[jn][3] = v3;
            tm0 = fmaxf(tm0, fmaxf(v0, v1));
            tm1 = fmaxf(tm1, fmaxf(v2, v3));
        }
        tm0 = fmaxf(tm0, __shfl_xor_sync(0xffffffffu, tm0, 1));
        tm0 = fmaxf(tm0, __shfl_xor_sync(0xffffffffu, tm0, 2));
        tm1 = fmaxf(tm1, __shfl_xor_sync(0xffffffffu, tm1, 1));
        tm1 = fmaxf(tm1, __shfl_xor_sync(0xffffffffu, tm1, 2));

        const float mn0 = fmaxf(m0, tm0);
        const float mn1 = fmaxf(m1, tm1);
        const float al0 = ex2f(m0 - mn0);
        const float al1 = ex2f(m1 - mn1);
        m0 = mn0; m1 = mn1;

        float s0 = 0.0f, s1 = 0.0f;
        #pragma unroll
        for (int jn = 0; jn < 8; jn++) {
            float p0 = ex2f(sacc[jn][0] - mn0);
            float p1 = ex2f(sacc[jn][1] - mn0);
            float p2 = ex2f(sacc[jn][2] - mn1);
            float p3 = ex2f(sacc[jn][3] - mn1);
            sacc[jn][0] = p0; sacc[jn][1] = p1;
            sacc[jn][2] = p2; sacc[jn][3] = p3;
            s0 += p0 + p1;
            s1 += p2 + p3;
        }
        s0 += __shfl_xor_sync(0xffffffffu, s0, 1);
        s0 += __shfl_xor_sync(0xffffffffu, s0, 2);
        s1 += __shfl_xor_sync(0xffffffffu, s1, 1);
        s1 += __shfl_xor_sync(0xffffffffu, s1, 2);
        l0 = l0 * al0 + s0;
        l1 = l1 * al1 + s1;

        // ---- rescale O, then O += P @ V ----
        #pragma unroll
        for (int jd = 0; jd < 8; jd++) {
            o[jd][0] *= al0; o[jd][1] *= al0;
            o[jd][2] *= al1; o[jd][3] *= al1;
        }

        #pragma unroll
        for (int kc = 0; kc < 4; kc++) {
            uint32_t ph[4], pl[4];
            {
                __half2 hh, ll;
                split2(sacc[2 * kc][0], sacc[2 * kc][1], hh, ll);
                ph[0] = h2u(hh); pl[0] = h2u(ll);
                split2(sacc[2 * kc][2], sacc[2 * kc][3], hh, ll);
                ph[1] = h2u(hh); pl[1] = h2u(ll);
                split2(sacc[2 * kc + 1][0], sacc[2 * kc + 1][1], hh, ll);
                ph[2] = h2u(hh); pl[2] = h2u(ll);
                split2(sacc[2 * kc + 1][2], sacc[2 * kc + 1][3], hh, ll);
                ph[3] = h2u(hh); pl[3] = h2u(ll);
            }
            #pragma unroll
            for (int jdp = 0; jdp < 4; jdp++) {
                const uint32_t voff =
                    2 * (((kc << 4) + lrow16) * KPITCH + (jdp << 4) + lhi8);
                uint32_t vh[4], vl[4];
                ldsm_x4_t(vh, sKV + AV_HI_B + voff);
                ldsm_x4_t(vl, sKV + AV_LO_B + voff);
                mma_f16(o[2 * jdp],     ph, vh);
                mma_f16(o[2 * jdp + 1], ph, vh + 2);
                mma_f16(o[2 * jdp],     ph, vl);
                mma_f16(o[2 * jdp + 1], ph, vl + 2);
                mma_f16(o[2 * jdp],     pl, vh);
                mma_f16(o[2 * jdp + 1], pl, vh + 2);
            }
        }
    }

    const float inv0 = 1.0f / l0;
    const float inv1 = 1.0f / l1;
    const size_t y0 = (size_t)(b * T_ + row0) * C_ + h * D_ + (tig << 1);
    const size_t y1 = y0 + 8 * (size_t)C_;
    #pragma unroll
    for (int jd = 0; jd < 8; jd++) {
        __half2 hh, ll;
        split2(o[jd][0] * inv0, o[jd][1] * inv0, hh, ll);
        *(__half2*)&yhi[y0 + (jd << 3)] = hh;
        *(__half2*)&ylo[y0 + (jd << 3)] = ll;
        split2(o[jd][2] * inv1, o[jd][3] * inv1, hh, ll);
        *(__half2*)&yhi[y1 + (jd << 3)] = hh;
        *(__half2*)&ylo[y1 + (jd << 3)] = ll;
    }
}

// ---------------------------------------------------------------------------
// Launch
// ---------------------------------------------------------------------------
extern "C" void kernel_launch(void* const* d_in, const int* in_sizes, int n_in,
                              void* d_out, int out_size)
{
    const float* x      = (const float*)d_in[0];
    const float* w_attn = (const float*)d_in[1];
    const float* b_attn = (const float*)d_in[2];
    const float* w_proj = (const float*)d_in[3];
    const float* b_proj = (const float*)d_in[4];
    float* out = (float*)d_out;

    __half *xhi, *xlo, *wahi, *walo, *wphi, *wplo, *qkvhi, *qkvlo, *yhi, *ylo;
    cudaGetSymbolAddress((void**)&xhi,   g_xhi);
    cudaGetSymbolAddress((void**)&xlo,   g_xlo);
    cudaGetSymbolAddress((void**)&wahi,  g_wahi);
    cudaGetSymbolAddress((void**)&walo,  g_walo);
    cudaGetSymbolAddress((void**)&wphi,  g_wphi);
    cudaGetSymbolAddress((void**)&wplo,  g_wplo);
    cudaGetSymbolAddress((void**)&qkvhi, g_qkvhi);
    cudaGetSymbolAddress((void**)&qkvlo, g_qkvlo);
    cudaGetSymbolAddress((void**)&yhi,   g_yhi);
    cudaGetSymbolAddress((void**)&ylo,   g_ylo);

    cudaFuncSetAttribute(gemm_h_kernel<1, 1>,
                         cudaFuncAttributeMaxDynamicSharedMemorySize,
                         GEMM_SMEM_BYTES);
    cudaFuncSetAttribute(gemm_h_kernel<0, 1>,
                         cudaFuncAttributeMaxDynamicSharedMemorySize,
                         GEMM_SMEM_BYTES);
    cudaFuncSetAttribute(gemm_h_kernel<0, 0>,
                         cudaFuncAttributeMaxDynamicSharedMemorySize,
                         GEMM_SMEM_BYTES);
    cudaFuncSetAttribute(attn_tc_kernel,
                         cudaFuncAttributeMaxDynamicSharedMemorySize,
                         ATTN_TC_SMEM);

    convert_x_kernel<<<(M_ * C_ / 4 + 255) / 256, 256>>>(x, xhi, xlo, M_ * C_ / 4);
    convert_wT_kernel<<<dim3(W3_ / 32, C_ / 32), 256>>>(w_attn, wahi, walo, C_, W3_);
    convert_wT_kernel<<<dim3(C_ / 32, C_ / 32), 256>>>(w_proj, wphi, wplo, C_, C_);

    // qk part of qkv (cols 0..2047): 3-term, feeds softmax amplifier
    gemm_h_kernel<1, 1><<<dim3(2 * C_ / 128, M_ / 128), 256, GEMM_SMEM_BYTES>>>(
        xhi, xlo, wahi, walo, b_attn, nullptr, qkvhi, qkvlo, M_, C_, W3_);

    // v part of qkv (cols 2048..3071): 2-term, enters y linearly
    gemm_h_kernel<0, 1><<<dim3(C_ / 128, M_ / 128), 256, GEMM_SMEM_BYTES>>>(
        xhi, xlo, wahi + (size_t)2 * C_ * C_, nullptr, b_attn + 2 * C_,
        nullptr, qkvhi + 2 * C_, qkvlo + 2 * C_, M_, C_, W3_);

    // y = causal_attention(q, k, v) -> split halves
    attn_tc_kernel<<<dim3(T_ / 128, H_, B_), 256, ATTN_TC_SMEM>>>(
        qkvhi, qkvlo, yhi, ylo);

    // out = y @ w_proj + b_proj (fp32; 2-term)
    gemm_h_kernel<0, 0><<<dim3(C_ / 128, M_ / 128), 256, GEMM_SMEM_BYTES>>>(
        yhi, ylo, wphi, wplo, b_proj, out, nullptr, nullptr, M_, C_, C_);
}

// round 16
// speedup vs baseline: 1.1555x; 1.0568x over previous
#include <cuda_runtime.h>
#include <cuda_fp16.h>
#include <cstdint>

// Problem constants
#define B_  4
#define T_  2048
#define C_  1024
#define H_  16
#define D_  64
#define M_  (B_ * T_)      // 8192 rows
#define W3_ (3 * C_)       // 3072

// Scratch (allocation-free rule: __device__ globals), all pre-split half data
__device__ __half g_xhi[(size_t)M_ * C_];
__device__ __half g_xlo[(size_t)M_ * C_];
__device__ __half g_wahi[(size_t)W3_ * C_];   // w_attn transposed [N][K]
__device__ __half g_walo[(size_t)W3_ * C_];
__device__ __half g_wphi[(size_t)C_ * C_];    // w_proj transposed [N][K]
__device__ __half g_wplo[(size_t)C_ * C_];
__device__ __half g_qkvhi[(size_t)M_ * W3_];
__device__ __half g_qkvlo[(size_t)M_ * W3_];
__device__ __half g_yhi[(size_t)M_ * C_];
__device__ __half g_ylo[(size_t)M_ * C_];

// ---------------------------------------------------------------------------
// helpers
// ---------------------------------------------------------------------------
__device__ __forceinline__ void mma_f16(float* acc, const uint32_t* a,
                                        const uint32_t* b) {
    asm volatile(
        "mma.sync.aligned.m16n8k16.row.col.f32.f16.f16.f32 "
        "{%0,%1,%2,%3}, {%4,%5,%6,%7}, {%8,%9}, {%0,%1,%2,%3};"
        : "+f"(acc[0]), "+f"(acc[1]), "+f"(acc[2]), "+f"(acc[3])
        : "r"(a[0]), "r"(a[1]), "r"(a[2]), "r"(a[3]),
          "r"(b[0]), "r"(b[1]));
}

__device__ __forceinline__ void split2(float x, float y, __half2& hi, __half2& lo) {
    hi = __float22half2_rn(make_float2(x, y));
    float2 h = __half22float2(hi);
    lo = __float22half2_rn(make_float2(x - h.x, y - h.y));
}

__device__ __forceinline__ uint32_t h2u(__half2 v) { return *(uint32_t*)&v; }

__device__ __forceinline__ float ex2f(float x) {
    float y;
    asm("ex2.approx.f32 %0, %1;" : "=f"(y) : "f"(x));
    return y;
}

__device__ __forceinline__ uint32_t smem_u32(const void* p) {
    uint32_t a;
    asm("{ .reg .u64 t; cvta.to.shared.u64 t, %1; cvt.u32.u64 %0, t; }"
        : "=r"(a) : "l"(p));
    return a;
}

__device__ __forceinline__ void ldsm_x4(uint32_t* r, uint32_t addr) {
    asm volatile("ldmatrix.sync.aligned.m8n8.x4.shared.b16 {%0,%1,%2,%3}, [%4];"
                 : "=r"(r[0]), "=r"(r[1]), "=r"(r[2]), "=r"(r[3]) : "r"(addr));
}
__device__ __forceinline__ void ldsm_x4_t(uint32_t* r, uint32_t addr) {
    asm volatile("ldmatrix.sync.aligned.m8n8.x4.trans.shared.b16 {%0,%1,%2,%3}, [%4];"
                 : "=r"(r[0]), "=r"(r[1]), "=r"(r[2]), "=r"(r[3]) : "r"(addr));
}

__device__ __forceinline__ void cp16(uint32_t saddr, const void* gptr) {
    asm volatile("cp.async.cg.shared.global [%0], [%1], 16;"
                 :: "r"(saddr), "l"(gptr) : "memory");
}
#define CP_COMMIT() asm volatile("cp.async.commit_group;" ::: "memory")
#define CP_WAIT(n)  asm volatile("cp.async.wait_group %0;" :: "n"(n) : "memory")

// ---------------------------------------------------------------------------
// Converter kernels
// ---------------------------------------------------------------------------
__global__ void __launch_bounds__(256) convert_x_kernel(
    const float* __restrict__ x, __half* __restrict__ xhi,
    __half* __restrict__ xlo, int n4)
{
    int i = blockIdx.x * 256 + threadIdx.x;
    if (i >= n4) return;
    float4 v = *(const float4*)(x + 4 * (size_t)i);
    __half2 h01, l01, h23, l23;
    split2(v.x, v.y, h01, l01);
    split2(v.z, v.w, h23, l23);
    *(__half2*)&xhi[4 * (size_t)i]     = h01;
    *(__half2*)&xhi[4 * (size_t)i + 2] = h23;
    *(__half2*)&xlo[4 * (size_t)i]     = l01;
    *(__half2*)&xlo[4 * (size_t)i + 2] = l23;
}

// W [K][N] fp32 -> Whi/Wlo [N][K] halves (transpose + split)
__global__ void __launch_bounds__(256) convert_wT_kernel(
    const float* __restrict__ W, __half* __restrict__ whi,
    __half* __restrict__ wlo, int K, int N)
{
    __shared__ float tile[32][33];
    const int tx = threadIdx.x & 31;
    const int ty = threadIdx.x >> 5;
    const int n0 = blockIdx.x * 32;
    const int k0 = blockIdx.y * 32;
    #pragma unroll
    for (int i = ty; i < 32; i += 8)
        tile[i][tx] = W[(size_t)(k0 + i) * N + n0 + tx];
    __syncthreads();
    #pragma unroll
    for (int i = ty; i < 32; i += 8) {
        float v = tile[tx][i];
        __half h = __float2half_rn(v);
        __half l = __float2half_rn(v - __half2float(h));
        whi[(size_t)(n0 + i) * K + k0 + tx] = h;
        wlo[(size_t)(n0 + i) * K + k0 + tx] = l;
    }
}

// ---------------------------------------------------------------------------
// Split-fp16 tensor GEMM, templated on THREE_TERM (no runtime branch).
// THREE_TERM=1: hh+hl+lh. THREE_TERM=0: hh+lh (B-lo never touched).
// 128x128 CTA tile, BK=32, 256 threads (8 warps 4Mx2N), cp.async pipeline.
// ---------------------------------------------------------------------------
#define APITCH 40
#define ST_ALO 10240
#define ST_BHI 20480
#define ST_BLO 30720
#define STAGE_B 40960
#define GEMM_SMEM_BYTES (2 * STAGE_B)     // 81920

template <int THREE_TERM, int WRITE_SPLIT>
__global__ void __launch_bounds__(256, 2) gemm_h_kernel(
    const __half* __restrict__ Ahi_g, const __half* __restrict__ Alo_g,
    const __half* __restrict__ Bhi_g, const __half* __restrict__ Blo_g,
    const float* __restrict__ bias,
    float* __restrict__ Out, __half* __restrict__ Ohi, __half* __restrict__ Olo,
    int M, int K, int N)
{
    extern __shared__ __half smh[];

    const int tid  = threadIdx.x;
    const int w    = tid >> 5;
    const int lane = tid & 31;
    const int g    = lane >> 2;
    const int tig  = lane & 3;
    const int wm   = (w & 3) * 32;
    const int wn   = (w >> 2) * 64;

    const int lrow16 = lane & 15;
    const int lhi8   = (lane & 16) >> 1;
    const int l8     = lane & 8;

    const int bm = blockIdx.y * 128;
    const int bn = blockIdx.x * 128;

    const int sr = tid >> 2;          // 0..63 (+64)
    const int sc = tid & 3;           // 16B chunk within row

    const uint32_t sbase = smem_u32(smh);

    float acc[2][8][4] = {};

    const int nchunk = K >> 5;

    const __half* gA  = Ahi_g + (size_t)(bm + sr) * K + 8 * sc;
    const __half* gAl = Alo_g + (size_t)(bm + sr) * K + 8 * sc;
    const __half* gB  = Bhi_g + (size_t)(bn + sr) * K + 8 * sc;
    const __half* gBl = Blo_g + (size_t)(bn + sr) * K + 8 * sc;
    const size_t rstep = 64 * (size_t)K;

    auto issue = [&](int c, int buf) {
        const int k0 = c << 5;
        const uint32_t S = sbase + (buf ? STAGE_B : 0);
        #pragma unroll
        for (int l = 0; l < 2; l++) {
            const uint32_t off = (uint32_t)(sr + 64 * l) * 80 + 16 * sc;
            cp16(S + off,          gA  + l * rstep + k0);
            cp16(S + ST_ALO + off, gAl + l * rstep + k0);
            cp16(S + ST_BHI + off, gB  + l * rstep + k0);
            if (THREE_TERM)
                cp16(S + ST_BLO + off, gBl + l * rstep + k0);
        }
        CP_COMMIT();
    };

    issue(0, 0);

    for (int c = 0; c < nchunk; c++) {
        CP_WAIT(0);
        __syncthreads();
        if (c + 1 < nchunk) issue(c + 1, (c + 1) & 1);

        const uint32_t sA = sbase + ((c & 1) ? STAGE_B : 0);

        #pragma unroll
        for (int ks = 0; ks < 2; ks++) {
            uint32_t ah[2][4], al[2][4];
            #pragma unroll
            for (int ti = 0; ti < 2; ti++) {
                const uint32_t aoff =
                    2 * ((wm + (ti << 4) + lrow16) * APITCH + (ks << 4) + lhi8);
                ldsm_x4(ah[ti], sA + aoff);
                ldsm_x4(al[ti], sA + ST_ALO + aoff);
            }
            #pragma unroll
            for (int jp = 0; jp < 4; jp++) {
                const uint32_t boff =
                    2 * ((wn + (jp << 4) + (lane & 7) + lhi8) * APITCH + (ks << 4) + l8);
                uint32_t bh[4], bl[4];
                ldsm_x4(bh, sA + ST_BHI + boff);
                if (THREE_TERM) ldsm_x4(bl, sA + ST_BLO + boff);
                // term-major ordering: same-acc distance = 4
                mma_f16(acc[0][2 * jp],     ah[0], bh);
                mma_f16(acc[0][2 * jp + 1], ah[0], bh + 2);
                mma_f16(acc[1][2 * jp],     ah[1], bh);
                mma_f16(acc[1][2 * jp + 1], ah[1], bh + 2);
                if (THREE_TERM) {
                    mma_f16(acc[0][2 * jp],     ah[0], bl);
                    mma_f16(acc[0][2 * jp + 1], ah[0], bl + 2);
                    mma_f16(acc[1][2 * jp],     ah[1], bl);
                    mma_f16(acc[1][2 * jp + 1], ah[1], bl + 2);
                }
                mma_f16(acc[0][2 * jp],     al[0], bh);
                mma_f16(acc[0][2 * jp + 1], al[0], bh + 2);
                mma_f16(acc[1][2 * jp],     al[1], bh);
                mma_f16(acc[1][2 * jp + 1], al[1], bh + 2);
            }
        }
    }

    // ---- epilogue ----
    if (WRITE_SPLIT) {
        #pragma unroll
        for (int j = 0; j < 8; j++) {
            const int col = bn + wn + (j << 3) + (tig << 1);
            const float2 bb = *(const float2*)(bias + col);
            #pragma unroll
            for (int ti = 0; ti < 2; ti++) {
                const int row = bm + wm + (ti << 4) + g;
                __half2 hh, ll;
                split2(acc[ti][j][0] + bb.x, acc[ti][j][1] + bb.y, hh, ll);
                *(__half2*)&Ohi[(size_t)row * N + col] = hh;
                *(__half2*)&Olo[(size_t)row * N + col] = ll;
                split2(acc[ti][j][2] + bb.x, acc[ti][j][3] + bb.y, hh, ll);
                *(__half2*)&Ohi[(size_t)(row + 8) * N + col] = hh;
                *(__half2*)&Olo[(size_t)(row + 8) * N + col] = ll;
            }
        }
    } else {
        #pragma unroll
        for (int j = 0; j < 8; j++) {
            const int col = bn + wn + (j << 3) + (tig << 1);
            const float2 bb = *(const float2*)(bias + col);
            #pragma unroll
            for (int ti = 0; ti < 2; ti++) {
                const int row = bm + wm + (ti << 4) + g;
                float2 o0, o1;
                o0.x = acc[ti][j][0] + bb.x;
                o0.y = acc[ti][j][1] + bb.y;
                o1.x = acc[ti][j][2] + bb.x;
                o1.y = acc[ti][j][3] + bb.y;
                *(float2*)(Out + (size_t)row * N + col)       = o0;
                *(float2*)(Out + (size_t)(row + 8) * N + col) = o1;
            }
        }
    }
}

// ---------------------------------------------------------------------------
// Split-fp16 TC causal flash attention.
// exp2-domain softmax, 2-term PV (ph*vh + ph*vl; pl dropped — error ~2.4e-4
// enters y linearly), qi reversal for causal load balance.
// ---------------------------------------------------------------------------
#define KPITCH 72
#define KV_STAGE 36864
#define AK_LO_B (64 * KPITCH * 2)
#define AV_HI_B (2 * 64 * KPITCH * 2)
#define AV_LO_B (3 * 64 * KPITCH * 2)
#define AQ_LO_B (128 * KPITCH * 2)
#define KV_BASE 36864
#define ATTN_TC_SMEM (KV_BASE + 2 * KV_STAGE)   // 110592
#define SM_SCALE 11.5415603f                     // 8 * log2(e)

__global__ void __launch_bounds__(256, 2) attn_tc_kernel(
    const __half* __restrict__ qkvhi, const __half* __restrict__ qkvlo,
    __half* __restrict__ yhi, __half* __restrict__ ylo)
{
    extern __shared__ __half sha[];

    const int tid  = threadIdx.x;
    const int w    = tid >> 5;
    const int lane = tid & 31;
    const int g    = lane >> 2;
    const int tig  = lane & 3;
    const int lrow16 = lane & 15;
    const int lhi8   = (lane & 16) >> 1;
    const int l8     = lane & 8;
    const int qi   = gridDim.x - 1 - blockIdx.x;   // heaviest CTAs first
    const int h    = blockIdx.y;
    const int b    = blockIdx.z;
    const int qblock = qi * 128;

    const uint32_t sbase = smem_u32(sha);
    const size_t rowbase = (size_t)b * T_ * W3_ + h * D_;

    const int sr = tid >> 3;
    const int sc = tid & 7;

    auto issue_kv = [&](int kj, int buf) {
        const uint32_t S = sbase + KV_BASE + (buf ? KV_STAGE : 0);
        #pragma unroll
        for (int l = 0; l < 2; l++) {
            const int r = sr + 32 * l;
            const size_t src = rowbase + (size_t)(kj * 64 + r) * W3_ + 8 * sc;
            const uint32_t off = (uint32_t)r * 144 + 16 * sc;
            cp16(S + off,           qkvhi + src + C_);
            cp16(S + AK_LO_B + off, qkvlo + src + C_);
            cp16(S + AV_HI_B + off, qkvhi + src + 2 * C_);
            cp16(S + AV_LO_B + off, qkvlo + src + 2 * C_);
        }
        CP_COMMIT();
    };

    issue_kv(0, 0);

    {
        char* S = (char*)sha;
        #pragma unroll
        for (int l = 0; l < 4; l++) {
            const int r = sr + 32 * l;
            const size_t src = rowbase + (size_t)(qblock + r) * W3_ + 8 * sc;
            const int off = r * 144 + 16 * sc;
            *(uint4*)(S + off)           = *(const uint4*)(qkvhi + src);
            *(uint4*)(S + AQ_LO_B + off) = *(const uint4*)(qkvlo + src);
        }
    }
    __syncthreads();

    uint32_t qh[4][4], ql[4][4];
    #pragma unroll
    for (int kc = 0; kc < 4; kc++) {
        const uint32_t qoff = 2 * (((w << 4) + lrow16) * KPITCH + (kc << 4) + lhi8);
        ldsm_x4(qh[kc], sbase + qoff);
        ldsm_x4(ql[kc], sbase + AQ_LO_B + qoff);
    }

    const int row0 = qblock + (w << 4) + g;
    const int row1 = row0 + 8;

    float m0 = -1e30f, m1 = -1e30f, l0 = 0.0f, l1 = 0.0f;
    float o[8][4] = {};

    const int nkj = 2 * qi + 2;

    for (int kj = 0; kj < nkj; kj++) {
        CP_WAIT(0);
        __syncthreads();
        if (kj + 1 < nkj) issue_kv(kj + 1, (kj + 1) & 1);

        const uint32_t sKV = sbase + KV_BASE + ((kj & 1) ? KV_STAGE : 0);

        // ---- S = Q @ K^T (3-term: feeds softmax) ----
        float sacc[8][4] = {};
        #pragma unroll
        for (int kc = 0; kc < 4; kc++) {
            #pragma unroll
            for (int jnp = 0; jnp < 4; jnp++) {
                const uint32_t koff =
                    2 * (((jnp << 4) + (lane & 7) + lhi8) * KPITCH + (kc << 4) + l8);
                uint32_t kh[4], kl[4];
                ldsm_x4(kh, sKV + koff);
                ldsm_x4(kl, sKV + AK_LO_B + koff);
                mma_f16(sacc[2 * jnp],     qh[kc], kh);
                mma_f16(sacc[2 * jnp + 1], qh[kc], kh + 2);
                mma_f16(sacc[2 * jnp],     qh[kc], kl);
                mma_f16(sacc[2 * jnp + 1], qh[kc], kl + 2);
                mma_f16(sacc[2 * jnp],     ql[kc], kh);
                mma_f16(sacc[2 * jnp + 1], ql[kc], kh + 2);
            }
        }

        // ---- mask + scale (exp2 domain) + online softmax ----
        float tm0 = -1e30f, tm1 = -1e30f;
        #pragma unroll
        for (int jn = 0; jn < 8; jn++) {
            const int c0 = kj * 64 + (jn << 3) + (tig << 1);
            float v0 = (c0     <= row0) ? sacc[jn][0] * SM_SCALE : -1e30f;
            float v1 = (c0 + 1 <= row0) ? sacc[jn][1] * SM_SCALE : -1e30f;
            float v2 = (c0     <= row1) ? sacc[jn][2] * SM_SCALE : -1e30f;
            float v3 = (c0 + 1 <= row1) ? sacc[jn][3] * SM_SCALE : -1e30f;
            sacc[jn][0] = v0; sacc[jn][1] = v1;
            sacc[jn][2] = v2; sacc[jn][3] = v3;
            tm0 = fmaxf(tm0, fmaxf(v0, v1));
            tm1 = fmaxf(tm1, fmaxf(v2, v3));
        }
        tm0 = fmaxf(tm0, __shfl_xor_sync(0xffffffffu, tm0, 1));
        tm0 = fmaxf(tm0, __shfl_xor_sync(0xffffffffu, tm0, 2));
        tm1 = fmaxf(tm1, __shfl_xor_sync(0xffffffffu, tm1, 1));
        tm1 = fmaxf(tm1, __shfl_xor_sync(0xffffffffu, tm1, 2));

        const float mn0 = fmaxf(m0, tm0);
        const float mn1 = fmaxf(m1, tm1);
        const float al0 = ex2f(m0 - mn0);
        const float al1 = ex2f(m1 - mn1);
        m0 = mn0; m1 = mn1;

        float s0 = 0.0f, s1 = 0.0f;
        #pragma unroll
        for (int jn = 0; jn < 8; jn++) {
            float p0 = ex2f(sacc[jn][0] - mn0);
            float p1 = ex2f(sacc[jn][1] - mn0);
            float p2 = ex2f(sacc[jn][2] - mn1);
            float p3 = ex2f(sacc[jn][3] - mn1);
            sacc[jn][0] = p0; sacc[jn][1] = p1;
            sacc[jn][2] = p2; sacc[jn][3] = p3;
            s0 += p0 + p1;
            s1 += p2 + p3;
        }
        s0 += __shfl_xor_sync(0xffffffffu, s0, 1);
        s0 += __shfl_xor_sync(0xffffffffu, s0, 2);
        s1 += __shfl_xor_sync(0xffffffffu, s1, 1);
        s1 += __shfl_xor_sync(0xffffffffu, s1, 2);
        l0 = l0 * al0 + s0;
        l1 = l1 * al1 + s1;

        // ---- rescale O, then O += P @ V (2-term: ph*vh + ph*vl) ----
        #pragma unroll
        for (int jd = 0; jd < 8; jd++) {
            o[jd][0] *= al0; o[jd][1] *= al0;
            o[jd][2] *= al1; o[jd][3] *= al1;
        }

        #pragma unroll
        for (int kc = 0; kc < 4; kc++) {
            uint32_t ph[4];
            ph[0] = h2u(__float22half2_rn(
                make_float2(sacc[2 * kc][0], sacc[2 * kc][1])));
            ph[1] = h2u(__float22half2_rn(
                make_float2(sacc[2 * kc][2], sacc[2 * kc][3])));
            ph[2] = h2u(__float22half2_rn(
                make_float2(sacc[2 * kc + 1][0], sacc[2 * kc + 1][1])));
            ph[3] = h2u(__float22half2_rn(
                make_float2(sacc[2 * kc + 1][2], sacc[2 * kc + 1][3])));
            #pragma unroll
            for (int jdp = 0; jdp < 4; jdp++) {
                const uint32_t voff =
                    2 * (((kc << 4) + lrow16) * KPITCH + (jdp << 4) + lhi8);
                uint32_t vh[4], vl[4];
                ldsm_x4_t(vh, sKV + AV_HI_B + voff);
                ldsm_x4_t(vl, sKV + AV_LO_B + voff);
                mma_f16(o[2 * jdp],     ph, vh);
                mma_f16(o[2 * jdp + 1], ph, vh + 2);
                mma_f16(o[2 * jdp],     ph, vl);
                mma_f16(o[2 * jdp + 1], ph, vl + 2);
            }
        }
    }

    const float inv0 = 1.0f / l0;
    const float inv1 = 1.0f / l1;
    const size_t y0 = (size_t)(b * T_ + row0) * C_ + h * D_ + (tig << 1);
    const size_t y1 = y0 + 8 * (size_t)C_;
    #pragma unroll
    for (int jd = 0; jd < 8; jd++) {
        __half2 hh, ll;
        split2(o[jd][0] * inv0, o[jd][1] * inv0, hh, ll);
        *(__half2*)&yhi[y0 + (jd << 3)] = hh;
        *(__half2*)&ylo[y0 + (jd << 3)] = ll;
        split2(o[jd][2] * inv1, o[jd][3] * inv1, hh, ll);
        *(__half2*)&yhi[y1 + (jd << 3)] = hh;
        *(__half2*)&ylo[y1 + (jd << 3)] = ll;
    }
}

// ---------------------------------------------------------------------------
// Launch
// ---------------------------------------------------------------------------
extern "C" void kernel_launch(void* const* d_in, const int* in_sizes, int n_in,
                              void* d_out, int out_size)
{
    const float* x      = (const float*)d_in[0];
    const float* w_attn = (const float*)d_in[1];
    const float* b_attn = (const float*)d_in[2];
    const float* w_proj = (const float*)d_in[3];
    const float* b_proj = (const float*)d_in[4];
    float* out = (float*)d_out;

    __half *xhi, *xlo, *wahi, *walo, *wphi, *wplo, *qkvhi, *qkvlo, *yhi, *ylo;
    cudaGetSymbolAddress((void**)&xhi,   g_xhi);
    cudaGetSymbolAddress((void**)&xlo,   g_xlo);
    cudaGetSymbolAddress((void**)&wahi,  g_wahi);
    cudaGetSymbolAddress((void**)&walo,  g_walo);
    cudaGetSymbolAddress((void**)&wphi,  g_wphi);
    cudaGetSymbolAddress((void**)&wplo,  g_wplo);
    cudaGetSymbolAddress((void**)&qkvhi, g_qkvhi);
    cudaGetSymbolAddress((void**)&qkvlo, g_qkvlo);
    cudaGetSymbolAddress((void**)&yhi,   g_yhi);
    cudaGetSymbolAddress((void**)&ylo,   g_ylo);

    cudaFuncSetAttribute(gemm_h_kernel<1, 1>,
                         cudaFuncAttributeMaxDynamicSharedMemorySize,
                         GEMM_SMEM_BYTES);
    cudaFuncSetAttribute(gemm_h_kernel<0, 1>,
                         cudaFuncAttributeMaxDynamicSharedMemorySize,
                         GEMM_SMEM_BYTES);
    cudaFuncSetAttribute(gemm_h_kernel<0, 0>,
                         cudaFuncAttributeMaxDynamicSharedMemorySize,
                         GEMM_SMEM_BYTES);
    cudaFuncSetAttribute(attn_tc_kernel,
                         cudaFuncAttributeMaxDynamicSharedMemorySize,
                         ATTN_TC_SMEM);

    convert_x_kernel<<<(M_ * C_ / 4 + 255) / 256, 256>>>(x, xhi, xlo, M_ * C_ / 4);
    convert_wT_kernel<<<dim3(W3_ / 32, C_ / 32), 256>>>(w_attn, wahi, walo, C_, W3_);
    convert_wT_kernel<<<dim3(C_ / 32, C_ / 32), 256>>>(w_proj, wphi, wplo, C_, C_);

    // qk part of qkv (cols 0..2047): 3-term, feeds softmax amplifier
    gemm_h_kernel<1, 1><<<dim3(2 * C_ / 128, M_ / 128), 256, GEMM_SMEM_BYTES>>>(
        xhi, xlo, wahi, walo, b_attn, nullptr, qkvhi, qkvlo, M_, C_, W3_);

    // v part of qkv (cols 2048..3071): 2-term, enters y linearly
    gemm_h_kernel<0, 1><<<dim3(C_ / 128, M_ / 128), 256, GEMM_SMEM_BYTES>>>(
        xhi, xlo, wahi + (size_t)2 * C_ * C_, nullptr, b_attn + 2 * C_,
        nullptr, qkvhi + 2 * C_, qkvlo + 2 * C_, M_, C_, W3_);

    // y = causal_attention(q, k, v) -> split halves
    attn_tc_kernel<<<dim3(T_ / 128, H_, B_), 256, ATTN_TC_SMEM>>>(
        qkvhi, qkvlo, yhi, ylo);

    // out = y @ w_proj + b_proj (fp32; 2-term)
    gemm_h_kernel<0, 0><<<dim3(C_ / 128, M_ / 128), 256, GEMM_SMEM_BYTES>>>(
        yhi, ylo, wphi, wplo, b_proj, out, nullptr, nullptr, M_, C_, C_);
}

// round 17
// speedup vs baseline: 1.2317x; 1.0660x over previous
#include <cuda_runtime.h>
#include <cuda_fp16.h>
#include <cstdint>

// Problem constants
#define B_  4
#define T_  2048
#define C_  1024
#define H_  16
#define D_  64
#define M_  (B_ * T_)      // 8192 rows
#define W3_ (3 * C_)       // 3072

// Scratch (allocation-free rule: __device__ globals), all pre-split half data
__device__ __half g_xhi[(size_t)M_ * C_];
__device__ __half g_xlo[(size_t)M_ * C_];
__device__ __half g_wahi[(size_t)W3_ * C_];   // w_attn transposed [N][K]
__device__ __half g_walo[(size_t)W3_ * C_];
__device__ __half g_wphi[(size_t)C_ * C_];    // w_proj transposed [N][K]
__device__ __half g_wplo[(size_t)C_ * C_];
__device__ __half g_qkvhi[(size_t)M_ * W3_];
__device__ __half g_qkvlo[(size_t)M_ * W3_];
__device__ __half g_yhi[(size_t)M_ * C_];
__device__ __half g_ylo[(size_t)M_ * C_];

// ---------------------------------------------------------------------------
// helpers
// ---------------------------------------------------------------------------
__device__ __forceinline__ void mma_f16(float* acc, const uint32_t* a,
                                        const uint32_t* b) {
    asm volatile(
        "mma.sync.aligned.m16n8k16.row.col.f32.f16.f16.f32 "
        "{%0,%1,%2,%3}, {%4,%5,%6,%7}, {%8,%9}, {%0,%1,%2,%3};"
        : "+f"(acc[0]), "+f"(acc[1]), "+f"(acc[2]), "+f"(acc[3])
        : "r"(a[0]), "r"(a[1]), "r"(a[2]), "r"(a[3]),
          "r"(b[0]), "r"(b[1]));
}

__device__ __forceinline__ void split2(float x, float y, __half2& hi, __half2& lo) {
    hi = __float22half2_rn(make_float2(x, y));
    float2 h = __half22float2(hi);
    lo = __float22half2_rn(make_float2(x - h.x, y - h.y));
}

__device__ __forceinline__ uint32_t h2u(__half2 v) { return *(uint32_t*)&v; }

__device__ __forceinline__ float ex2f(float x) {
    float y;
    asm("ex2.approx.f32 %0, %1;" : "=f"(y) : "f"(x));
    return y;
}

__device__ __forceinline__ uint32_t smem_u32(const void* p) {
    uint32_t a;
    asm("{ .reg .u64 t; cvta.to.shared.u64 t, %1; cvt.u32.u64 %0, t; }"
        : "=r"(a) : "l"(p));
    return a;
}

__device__ __forceinline__ void ldsm_x4(uint32_t* r, uint32_t addr) {
    asm volatile("ldmatrix.sync.aligned.m8n8.x4.shared.b16 {%0,%1,%2,%3}, [%4];"
                 : "=r"(r[0]), "=r"(r[1]), "=r"(r[2]), "=r"(r[3]) : "r"(addr));
}
__device__ __forceinline__ void ldsm_x4_t(uint32_t* r, uint32_t addr) {
    asm volatile("ldmatrix.sync.aligned.m8n8.x4.trans.shared.b16 {%0,%1,%2,%3}, [%4];"
                 : "=r"(r[0]), "=r"(r[1]), "=r"(r[2]), "=r"(r[3]) : "r"(addr));
}

__device__ __forceinline__ void cp16(uint32_t saddr, const void* gptr) {
    asm volatile("cp.async.cg.shared.global [%0], [%1], 16;"
                 :: "r"(saddr), "l"(gptr) : "memory");
}
#define CP_COMMIT() asm volatile("cp.async.commit_group;" ::: "memory")
#define CP_WAIT(n)  asm volatile("cp.async.wait_group %0;" :: "n"(n) : "memory")

// ---------------------------------------------------------------------------
// Converter kernels
// ---------------------------------------------------------------------------
__global__ void __launch_bounds__(256) convert_x_kernel(
    const float* __restrict__ x, __half* __restrict__ xhi,
    __half* __restrict__ xlo, int n4)
{
    int i = blockIdx.x * 256 + threadIdx.x;
    if (i >= n4) return;
    float4 v = *(const float4*)(x + 4 * (size_t)i);
    __half2 h01, l01, h23, l23;
    split2(v.x, v.y, h01, l01);
    split2(v.z, v.w, h23, l23);
    *(__half2*)&xhi[4 * (size_t)i]     = h01;
    *(__half2*)&xhi[4 * (size_t)i + 2] = h23;
    *(__half2*)&xlo[4 * (size_t)i]     = l01;
    *(__half2*)&xlo[4 * (size_t)i + 2] = l23;
}

// W [K][N] fp32 -> Whi/Wlo [N][K] halves (transpose + split)
__global__ void __launch_bounds__(256) convert_wT_kernel(
    const float* __restrict__ W, __half* __restrict__ whi,
    __half* __restrict__ wlo, int K, int N)
{
    __shared__ float tile[32][33];
    const int tx = threadIdx.x & 31;
    const int ty = threadIdx.x >> 5;
    const int n0 = blockIdx.x * 32;
    const int k0 = blockIdx.y * 32;
    #pragma unroll
    for (int i = ty; i < 32; i += 8)
        tile[i][tx] = W[(size_t)(k0 + i) * N + n0 + tx];
    __syncthreads();
    #pragma unroll
    for (int i = ty; i < 32; i += 8) {
        float v = tile[tx][i];
        __half h = __float2half_rn(v);
        __half l = __float2half_rn(v - __half2float(h));
        whi[(size_t)(n0 + i) * K + k0 + tx] = h;
        wlo[(size_t)(n0 + i) * K + k0 + tx] = l;
    }
}

// ---------------------------------------------------------------------------
// Split-fp16 tensor GEMM, templated (no runtime branch).
// THREE_TERM=1: hh+hl+lh. THREE_TERM=0: hh+lh (B-lo never touched).
// WRITE_SPLIT: 0 = fp32 Out, 1 = split hi/lo halves, 2 = hi-only halves.
// 128x128 CTA tile, BK=32, 256 threads (8 warps 4Mx2N), cp.async pipeline.
// ---------------------------------------------------------------------------
#define APITCH 40
#define ST_ALO 10240
#define ST_BHI 20480
#define ST_BLO 30720
#define STAGE_B 40960
#define GEMM_SMEM_BYTES (2 * STAGE_B)     // 81920

template <int THREE_TERM, int WRITE_SPLIT>
__global__ void __launch_bounds__(256, 2) gemm_h_kernel(
    const __half* __restrict__ Ahi_g, const __half* __restrict__ Alo_g,
    const __half* __restrict__ Bhi_g, const __half* __restrict__ Blo_g,
    const float* __restrict__ bias,
    float* __restrict__ Out, __half* __restrict__ Ohi, __half* __restrict__ Olo,
    int M, int K, int N)
{
    extern __shared__ __half smh[];

    const int tid  = threadIdx.x;
    const int w    = tid >> 5;
    const int lane = tid & 31;
    const int g    = lane >> 2;
    const int tig  = lane & 3;
    const int wm   = (w & 3) * 32;
    const int wn   = (w >> 2) * 64;

    const int lrow16 = lane & 15;
    const int lhi8   = (lane & 16) >> 1;
    const int l8     = lane & 8;

    const int bm = blockIdx.y * 128;
    const int bn = blockIdx.x * 128;

    const int sr = tid >> 2;          // 0..63 (+64)
    const int sc = tid & 3;           // 16B chunk within row

    const uint32_t sbase = smem_u32(smh);

    float acc[2][8][4] = {};

    const int nchunk = K >> 5;

    const __half* gA  = Ahi_g + (size_t)(bm + sr) * K + 8 * sc;
    const __half* gAl = Alo_g + (size_t)(bm + sr) * K + 8 * sc;
    const __half* gB  = Bhi_g + (size_t)(bn + sr) * K + 8 * sc;
    const __half* gBl = Blo_g + (size_t)(bn + sr) * K + 8 * sc;
    const size_t rstep = 64 * (size_t)K;

    auto issue = [&](int c, int buf) {
        const int k0 = c << 5;
        const uint32_t S = sbase + (buf ? STAGE_B : 0);
        #pragma unroll
        for (int l = 0; l < 2; l++) {
            const uint32_t off = (uint32_t)(sr + 64 * l) * 80 + 16 * sc;
            cp16(S + off,          gA  + l * rstep + k0);
            cp16(S + ST_ALO + off, gAl + l * rstep + k0);
            cp16(S + ST_BHI + off, gB  + l * rstep + k0);
            if (THREE_TERM)
                cp16(S + ST_BLO + off, gBl + l * rstep + k0);
        }
        CP_COMMIT();
    };

    issue(0, 0);

    for (int c = 0; c < nchunk; c++) {
        CP_WAIT(0);
        __syncthreads();
        if (c + 1 < nchunk) issue(c + 1, (c + 1) & 1);

        const uint32_t sA = sbase + ((c & 1) ? STAGE_B : 0);

        #pragma unroll
        for (int ks = 0; ks < 2; ks++) {
            uint32_t ah[2][4], al[2][4];
            #pragma unroll
            for (int ti = 0; ti < 2; ti++) {
                const uint32_t aoff =
                    2 * ((wm + (ti << 4) + lrow16) * APITCH + (ks << 4) + lhi8);
                ldsm_x4(ah[ti], sA + aoff);
                ldsm_x4(al[ti], sA + ST_ALO + aoff);
            }
            #pragma unroll
            for (int jp = 0; jp < 4; jp++) {
                const uint32_t boff =
                    2 * ((wn + (jp << 4) + (lane & 7) + lhi8) * APITCH + (ks << 4) + l8);
                uint32_t bh[4], bl[4];
                ldsm_x4(bh, sA + ST_BHI + boff);
                if (THREE_TERM) ldsm_x4(bl, sA + ST_BLO + boff);
                // term-major ordering: same-acc distance = 4
                mma_f16(acc[0][2 * jp],     ah[0], bh);
                mma_f16(acc[0][2 * jp + 1], ah[0], bh + 2);
                mma_f16(acc[1][2 * jp],     ah[1], bh);
                mma_f16(acc[1][2 * jp + 1], ah[1], bh + 2);
                if (THREE_TERM) {
                    mma_f16(acc[0][2 * jp],     ah[0], bl);
                    mma_f16(acc[0][2 * jp + 1], ah[0], bl + 2);
                    mma_f16(acc[1][2 * jp],     ah[1], bl);
                    mma_f16(acc[1][2 * jp + 1], ah[1], bl + 2);
                }
                mma_f16(acc[0][2 * jp],     al[0], bh);
                mma_f16(acc[0][2 * jp + 1], al[0], bh + 2);
                mma_f16(acc[1][2 * jp],     al[1], bh);
                mma_f16(acc[1][2 * jp + 1], al[1], bh + 2);
            }
        }
    }

    // ---- epilogue ----
    if (WRITE_SPLIT == 1) {
        #pragma unroll
        for (int j = 0; j < 8; j++) {
            const int col = bn + wn + (j << 3) + (tig << 1);
            const float2 bb = *(const float2*)(bias + col);
            #pragma unroll
            for (int ti = 0; ti < 2; ti++) {
                const int row = bm + wm + (ti << 4) + g;
                __half2 hh, ll;
                split2(acc[ti][j][0] + bb.x, acc[ti][j][1] + bb.y, hh, ll);
                *(__half2*)&Ohi[(size_t)row * N + col] = hh;
                *(__half2*)&Olo[(size_t)row * N + col] = ll;
                split2(acc[ti][j][2] + bb.x, acc[ti][j][3] + bb.y, hh, ll);
                *(__half2*)&Ohi[(size_t)(row + 8) * N + col] = hh;
                *(__half2*)&Olo[(size_t)(row + 8) * N + col] = ll;
            }
        }
    } else if (WRITE_SPLIT == 2) {
        #pragma unroll
        for (int j = 0; j < 8; j++) {
            const int col = bn + wn + (j << 3) + (tig << 1);
            const float2 bb = *(const float2*)(bias + col);
            #pragma unroll
            for (int ti = 0; ti < 2; ti++) {
                const int row = bm + wm + (ti << 4) + g;
                *(__half2*)&Ohi[(size_t)row * N + col] = __float22half2_rn(
                    make_float2(acc[ti][j][0] + bb.x, acc[ti][j][1] + bb.y));
                *(__half2*)&Ohi[(size_t)(row + 8) * N + col] = __float22half2_rn(
                    make_float2(acc[ti][j][2] + bb.x, acc[ti][j][3] + bb.y));
            }
        }
    } else {
        #pragma unroll
        for (int j = 0; j < 8; j++) {
            const int col = bn + wn + (j << 3) + (tig << 1);
            const float2 bb = *(const float2*)(bias + col);
            #pragma unroll
            for (int ti = 0; ti < 2; ti++) {
                const int row = bm + wm + (ti << 4) + g;
                float2 o0, o1;
                o0.x = acc[ti][j][0] + bb.x;
                o0.y = acc[ti][j][1] + bb.y;
                o1.x = acc[ti][j][2] + bb.x;
                o1.y = acc[ti][j][3] + bb.y;
                *(float2*)(Out + (size_t)row * N + col)       = o0;
                *(float2*)(Out + (size_t)(row + 8) * N + col) = o1;
            }
        }
    }
}

// ---------------------------------------------------------------------------
// Split-fp16 TC causal flash attention.
// exp2-domain softmax, 1-term PV (ph*vh only; V-lo never staged),
// qi reversal for causal load balance.
// SMEM: Q region 36864 + 2 x KV stage 27648 = 92160 B (2 CTAs/SM).
// ---------------------------------------------------------------------------
#define KPITCH 72
#define KV_STAGE 27648                    // Khi@0 Klo@9216 Vhi@18432
#define AK_LO_B (64 * KPITCH * 2)         //  9216
#define AV_HI_B (2 * 64 * KPITCH * 2)     // 18432
#define AQ_LO_B (128 * KPITCH * 2)        // 18432 within Q region
#define KV_BASE 36864
#define ATTN_TC_SMEM (KV_BASE + 2 * KV_STAGE)   // 92160
#define SM_SCALE 11.5415603f                     // 8 * log2(e)

__global__ void __launch_bounds__(256, 2) attn_tc_kernel(
    const __half* __restrict__ qkvhi, const __half* __restrict__ qkvlo,
    __half* __restrict__ yhi, __half* __restrict__ ylo)
{
    extern __shared__ __half sha[];

    const int tid  = threadIdx.x;
    const int w    = tid >> 5;
    const int lane = tid & 31;
    const int g    = lane >> 2;
    const int tig  = lane & 3;
    const int lrow16 = lane & 15;
    const int lhi8   = (lane & 16) >> 1;
    const int l8     = lane & 8;
    const int qi   = gridDim.x - 1 - blockIdx.x;   // heaviest CTAs first
    const int h    = blockIdx.y;
    const int b    = blockIdx.z;
    const int qblock = qi * 128;

    const uint32_t sbase = smem_u32(sha);
    const size_t rowbase = (size_t)b * T_ * W3_ + h * D_;

    const int sr = tid >> 3;
    const int sc = tid & 7;

    auto issue_kv = [&](int kj, int buf) {
        const uint32_t S = sbase + KV_BASE + (buf ? KV_STAGE : 0);
        #pragma unroll
        for (int l = 0; l < 2; l++) {
            const int r = sr + 32 * l;
            const size_t src = rowbase + (size_t)(kj * 64 + r) * W3_ + 8 * sc;
            const uint32_t off = (uint32_t)r * 144 + 16 * sc;
            cp16(S + off,           qkvhi + src + C_);
            cp16(S + AK_LO_B + off, qkvlo + src + C_);
            cp16(S + AV_HI_B + off, qkvhi + src + 2 * C_);
        }
        CP_COMMIT();
    };

    issue_kv(0, 0);

    {
        char* S = (char*)sha;
        #pragma unroll
        for (int l = 0; l < 4; l++) {
            const int r = sr + 32 * l;
            const size_t src = rowbase + (size_t)(qblock + r) * W3_ + 8 * sc;
            const int off = r * 144 + 16 * sc;
            *(uint4*)(S + off)           = *(const uint4*)(qkvhi + src);
            *(uint4*)(S + AQ_LO_B + off) = *(const uint4*)(qkvlo + src);
        }
    }
    __syncthreads();

    uint32_t qh[4][4], ql[4][4];
    #pragma unroll
    for (int kc = 0; kc < 4; kc++) {
        const uint32_t qoff = 2 * (((w << 4) + lrow16) * KPITCH + (kc << 4) + lhi8);
        ldsm_x4(qh[kc], sbase + qoff);
        ldsm_x4(ql[kc], sbase + AQ_LO_B + qoff);
    }

    const int row0 = qblock + (w << 4) + g;
    const int row1 = row0 + 8;

    float m0 = -1e30f, m1 = -1e30f, l0 = 0.0f, l1 = 0.0f;
    float o[8][4] = {};

    const int nkj = 2 * qi + 2;

    for (int kj = 0; kj < nkj; kj++) {
        CP_WAIT(0);
        __syncthreads();
        if (kj + 1 < nkj) issue_kv(kj + 1, (kj + 1) & 1);

        const uint32_t sKV = sbase + KV_BASE + ((kj & 1) ? KV_STAGE : 0);

        // ---- S = Q @ K^T (3-term: feeds softmax) ----
        float sacc[8][4] = {};
        #pragma unroll
        for (int kc = 0; kc < 4; kc++) {
            #pragma unroll
            for (int jnp = 0; jnp < 4; jnp++) {
                const uint32_t koff =
                    2 * (((jnp << 4) + (lane & 7) + lhi8) * KPITCH + (kc << 4) + l8);
                uint32_t kh[4], kl[4];
                ldsm_x4(kh, sKV + koff);
                ldsm_x4(kl, sKV + AK_LO_B + koff);
                mma_f16(sacc[2 * jnp],     qh[kc], kh);
                mma_f16(sacc[2 * jnp + 1], qh[kc], kh + 2);
                mma_f16(sacc[2 * jnp],     qh[kc], kl);
                mma_f16(sacc[2 * jnp + 1], qh[kc], kl + 2);
                mma_f16(sacc[2 * jnp],     ql[kc], kh);
                mma_f16(sacc[2 * jnp + 1], ql[kc], kh + 2);
            }
        }

        // ---- mask + scale (exp2 domain) + online softmax ----
        float tm0 = -1e30f, tm1 = -1e30f;
        #pragma unroll
        for (int jn = 0; jn < 8; jn++) {
            const int c0 = kj * 64 + (jn << 3) + (tig << 1);
            float v0 = (c0     <= row0) ? sacc[jn][0] * SM_SCALE : -1e30f;
            float v1 = (c0 + 1 <= row0) ? sacc[jn][1] * SM_SCALE : -1e30f;
            float v2 = (c0     <= row1) ? sacc[jn][2] * SM_SCALE : -1e30f;
            float v3 = (c0 + 1 <= row1) ? sacc[jn][3] * SM_SCALE : -1e30f;
            sacc[jn][0] = v0; sacc[jn][1] = v1;
            sacc[jn][2] = v2; sacc[jn][3] = v3;
            tm0 = fmaxf(tm0, fmaxf(v0, v1));
            tm1 = fmaxf(tm1, fmaxf(v2, v3));
        }
        tm0 = fmaxf(tm0, __shfl_xor_sync(0xffffffffu, tm0, 1));
        tm0 = fmaxf(tm0, __shfl_xor_sync(0xffffffffu, tm0, 2));
        tm1 = fmaxf(tm1, __shfl_xor_sync(0xffffffffu, tm1, 1));
        tm1 = fmaxf(tm1, __shfl_xor_sync(0xffffffffu, tm1, 2));

        const float mn0 = fmaxf(m0, tm0);
        const float mn1 = fmaxf(m1, tm1);
        const float al0 = ex2f(m0 - mn0);
        const float al1 = ex2f(m1 - mn1);
        m0 = mn0; m1 = mn1;

        float s0 = 0.0f, s1 = 0.0f;
        #pragma unroll
        for (int jn = 0; jn < 8; jn++) {
            float p0 = ex2f(sacc[jn][0] - mn0);
            float p1 = ex2f(sacc[jn][1] - mn0);
            float p2 = ex2f(sacc[jn][2] - mn1);
            float p3 = ex2f(sacc[jn][3] - mn1);
            sacc[jn][0] = p0; sacc[jn][1] = p1;
            sacc[jn][2] = p2; sacc[jn][3] = p3;
            s0 += p0 + p1;
            s1 += p2 + p3;
        }
        s0 += __shfl_xor_sync(0xffffffffu, s0, 1);
        s0 += __shfl_xor_sync(0xffffffffu, s0, 2);
        s1 += __shfl_xor_sync(0xffffffffu, s1, 1);
        s1 += __shfl_xor_sync(0xffffffffu, s1, 2);
        l0 = l0 * al0 + s0;
        l1 = l1 * al1 + s1;

        // ---- rescale O, then O += P @ V (1-term: ph*vh) ----
        #pragma unroll
        for (int jd = 0; jd < 8; jd++) {
            o[jd][0] *= al0; o[jd][1] *= al0;
            o[jd][2] *= al1; o[jd][3] *= al1;
        }

        #pragma unroll
        for (int kc = 0; kc < 4; kc++) {
            uint32_t ph[4];
            ph[0] = h2u(__float22half2_rn(
                make_float2(sacc[2 * kc][0], sacc[2 * kc][1])));
            ph[1] = h2u(__float22half2_rn(
                make_float2(sacc[2 * kc][2], sacc[2 * kc][3])));
            ph[2] = h2u(__float22half2_rn(
                make_float2(sacc[2 * kc + 1][0], sacc[2 * kc + 1][1])));
            ph[3] = h2u(__float22half2_rn(
                make_float2(sacc[2 * kc + 1][2], sacc[2 * kc + 1][3])));
            #pragma unroll
            for (int jdp = 0; jdp < 4; jdp++) {
                const uint32_t voff =
                    2 * (((kc << 4) + lrow16) * KPITCH + (jdp << 4) + lhi8);
                uint32_t vh[4];
                ldsm_x4_t(vh, sKV + AV_HI_B + voff);
                mma_f16(o[2 * jdp],     ph, vh);
                mma_f16(o[2 * jdp + 1], ph, vh + 2);
            }
        }
    }

    const float inv0 = 1.0f / l0;
    const float inv1 = 1.0f / l1;
    const size_t y0 = (size_t)(b * T_ + row0) * C_ + h * D_ + (tig << 1);
    const size_t y1 = y0 + 8 * (size_t)C_;
    #pragma unroll
    for (int jd = 0; jd < 8; jd++) {
        __half2 hh, ll;
        split2(o[jd][0] * inv0, o[jd][1] * inv0, hh, ll);
        *(__half2*)&yhi[y0 + (jd << 3)] = hh;
        *(__half2*)&ylo[y0 + (jd << 3)] = ll;
        split2(o[jd][2] * inv1, o[jd][3] * inv1, hh, ll);
        *(__half2*)&yhi[y1 + (jd << 3)] = hh;
        *(__half2*)&ylo[y1 + (jd << 3)] = ll;
    }
}

// ---------------------------------------------------------------------------
// Launch
// ---------------------------------------------------------------------------
extern "C" void kernel_launch(void* const* d_in, const int* in_sizes, int n_in,
                              void* d_out, int out_size)
{
    const float* x      = (const float*)d_in[0];
    const float* w_attn = (const float*)d_in[1];
    const float* b_attn = (const float*)d_in[2];
    const float* w_proj = (const float*)d_in[3];
    const float* b_proj = (const float*)d_in[4];
    float* out = (float*)d_out;

    __half *xhi, *xlo, *wahi, *walo, *wphi, *wplo, *qkvhi, *qkvlo, *yhi, *ylo;
    cudaGetSymbolAddress((void**)&xhi,   g_xhi);
    cudaGetSymbolAddress((void**)&xlo,   g_xlo);
    cudaGetSymbolAddress((void**)&wahi,  g_wahi);
    cudaGetSymbolAddress((void**)&walo,  g_walo);
    cudaGetSymbolAddress((void**)&wphi,  g_wphi);
    cudaGetSymbolAddress((void**)&wplo,  g_wplo);
    cudaGetSymbolAddress((void**)&qkvhi, g_qkvhi);
    cudaGetSymbolAddress((void**)&qkvlo, g_qkvlo);
    cudaGetSymbolAddress((void**)&yhi,   g_yhi);
    cudaGetSymbolAddress((void**)&ylo,   g_ylo);

    cudaFuncSetAttribute(gemm_h_kernel<1, 1>,
                         cudaFuncAttributeMaxDynamicSharedMemorySize,
                         GEMM_SMEM_BYTES);
    cudaFuncSetAttribute(gemm_h_kernel<0, 2>,
                         cudaFuncAttributeMaxDynamicSharedMemorySize,
                         GEMM_SMEM_BYTES);
    cudaFuncSetAttribute(gemm_h_kernel<0, 0>,
                         cudaFuncAttributeMaxDynamicSharedMemorySize,
                         GEMM_SMEM_BYTES);
    cudaFuncSetAttribute(attn_tc_kernel,
                         cudaFuncAttributeMaxDynamicSharedMemorySize,
                         ATTN_TC_SMEM);

    convert_x_kernel<<<(M_ * C_ / 4 + 255) / 256, 256>>>(x, xhi, xlo, M_ * C_ / 4);
    convert_wT_kernel<<<dim3(W3_ / 32, C_ / 32), 256>>>(w_attn, wahi, walo, C_, W3_);
    convert_wT_kernel<<<dim3(C_ / 32, C_ / 32), 256>>>(w_proj, wphi, wplo, C_, C_);

    // qk part of qkv (cols 0..2047): 3-term, feeds softmax amplifier
    gemm_h_kernel<1, 1><<<dim3(2 * C_ / 128, M_ / 128), 256, GEMM_SMEM_BYTES>>>(
        xhi, xlo, wahi, walo, b_attn, nullptr, qkvhi, qkvlo, M_, C_, W3_);

    // v part of qkv (cols 2048..3071): 2-term, hi-only output (PV is 1-term)
    gemm_h_kernel<0, 2><<<dim3(C_ / 128, M_ / 128), 256, GEMM_SMEM_BYTES>>>(
        xhi, xlo, wahi + (size_t)2 * C_ * C_, nullptr, b_attn + 2 * C_,
        nullptr, qkvhi + 2 * C_, nullptr, M_, C_, W3_);

    // y = causal_attention(q, k, v) -> split halves
    attn_tc_kernel<<<dim3(T_ / 128, H_, B_), 256, ATTN_TC_SMEM>>>(
        qkvhi, qkvlo, yhi, ylo);

    // out = y @ w_proj + b_proj (fp32; 2-term)
    gemm_h_kernel<0, 0><<<dim3(C_ / 128, M_ / 128), 256, GEMM_SMEM_BYTES>>>(
        yhi, ylo, wphi, wplo, b_proj, out, nullptr, nullptr, M_, C_, C_);
}